// round 3
// baseline (speedup 1.0000x reference)
#include <cuda_runtime.h>
#include <math.h>

// Problem constants
#define BB 2
#define TT 2048
#define HH 8
#define DD 32
// LAMBDA_INIT = 0.8 - 0.6*exp(-0.3)
#define LAMBDA_INIT 0.355509067591f
#define ONE_MINUS_LI 0.644490932409f
#define Q_SCALE 0.17677669529663687f  // 32^-0.5

// Scratch (device globals; no allocations allowed)
__device__ float q_s[(size_t)BB * 16 * TT * 32];   // [B,2H,T,D]
__device__ float k_s[(size_t)BB * 16 * TT * 32];   // [B,2H,T,D]
__device__ float v_s[(size_t)BB * 8 * TT * 64];    // [B,H,T,2D]
__device__ float attn_s[(size_t)BB * TT * 512];    // [B,T,E]
__device__ float g_lam;

// ---------------------------------------------------------------------------
// Kernel 1: fused QKV GEMM.  C[4096,1536] = X[4096,1024] @ [Wq | Wkv]
// Epilogue scatters into q_s (scaled), k_s, v_s head-major layouts.
// ---------------------------------------------------------------------------
__global__ __launch_bounds__(256) void gemm_qkv_kernel(
    const float* __restrict__ X,
    const float* __restrict__ Wq,
    const float* __restrict__ Wkv)
{
    const int n0 = blockIdx.x * 128;   // [0,1536)
    const int m0 = blockIdx.y * 128;   // [0,4096)
    const float* Bmat;
    int ldb;
    if (n0 < 512) { Bmat = Wq + n0; ldb = 512; }
    else          { Bmat = Wkv + (n0 - 512); ldb = 1024; }

    __shared__ float As[16][128];
    __shared__ float Bs[16][128];
    float acc[8][8] = {};

    const int tid = threadIdx.x;
    const int tx = tid & 15, ty = tid >> 4;

    for (int kt = 0; kt < 1024; kt += 16) {
#pragma unroll
        for (int it = 0; it < 2; it++) {
            int f = tid + it * 256;
            int row = f >> 2, kq = (f & 3) * 4;
            float4 a = *(const float4*)&X[(size_t)(m0 + row) * 1024 + kt + kq];
            As[kq + 0][row] = a.x; As[kq + 1][row] = a.y;
            As[kq + 2][row] = a.z; As[kq + 3][row] = a.w;
        }
#pragma unroll
        for (int it = 0; it < 2; it++) {
            int f = tid + it * 256;
            int row = f >> 5, cq = (f & 31) * 4;
            *(float4*)&Bs[row][cq] = *(const float4*)&Bmat[(size_t)(kt + row) * ldb + cq];
        }
        __syncthreads();
#pragma unroll
        for (int k = 0; k < 16; k++) {
            float a[8], bb[8];
            *(float4*)&a[0] = *(const float4*)&As[k][ty * 8];
            *(float4*)&a[4] = *(const float4*)&As[k][ty * 8 + 4];
            *(float4*)&bb[0] = *(const float4*)&Bs[k][tx * 8];
            *(float4*)&bb[4] = *(const float4*)&Bs[k][tx * 8 + 4];
#pragma unroll
            for (int i = 0; i < 8; i++)
#pragma unroll
                for (int j = 0; j < 8; j++)
                    acc[i][j] = fmaf(a[i], bb[j], acc[i][j]);
        }
        __syncthreads();
    }

    // Scatter epilogue (branch is uniform per block: n-tile within one segment)
#pragma unroll
    for (int i = 0; i < 8; i++) {
        int m = m0 + ty * 8 + i;
        int b = m >> 11;        // /2048
        int t = m & 2047;
#pragma unroll
        for (int j = 0; j < 8; j++) {
            int n = n0 + tx * 8 + j;
            float v = acc[i][j];
            if (n0 < 512) {
                int hh = n >> 5, d = n & 31;
                q_s[(((size_t)(b * 16 + hh)) * TT + t) * 32 + d] = v * Q_SCALE;
            } else if (n0 < 1024) {
                int c = n - 512;
                int hh = c >> 5, d = c & 31;
                k_s[(((size_t)(b * 16 + hh)) * TT + t) * 32 + d] = v;
            } else {
                int c = n - 1024;
                int hd = c >> 6, dd = c & 63;
                v_s[(((size_t)(b * 8 + hd)) * TT + t) * 64 + dd] = v;
            }
        }
    }
}

// ---------------------------------------------------------------------------
// Kernel 2: lambda scalar
// ---------------------------------------------------------------------------
__global__ void lam_kernel(const float* __restrict__ lq1, const float* __restrict__ lk1,
                           const float* __restrict__ lq2, const float* __restrict__ lk2)
{
    int lane = threadIdx.x;  // 32 threads, D=32
    float p1 = lq1[lane] * lk1[lane];
    float p2 = lq2[lane] * lk2[lane];
#pragma unroll
    for (int o = 16; o; o >>= 1) {
        p1 += __shfl_xor_sync(0xffffffffu, p1, o);
        p2 += __shfl_xor_sync(0xffffffffu, p2, o);
    }
    if (lane == 0) g_lam = expf(p1) - expf(p2) + LAMBDA_INIT;
}

// ---------------------------------------------------------------------------
// Kernel 3: differential flash attention + RMS-norm epilogue
// One block per (b, h, 64-row q tile). Two softmax streams (heads 2h, 2h+1).
// ---------------------------------------------------------------------------
#define SST 68  // padded stride for P tiles ([key][qrow])
#define ATTN_SMEM_BYTES ((4*2048 + 4096 + 2*64*SST + 6*64) * 4)

__global__ __launch_bounds__(256, 2) void attn_kernel(const float* __restrict__ gamma)
{
    extern __shared__ float sm[];
    float* Qs0 = sm;                  // [32][64] (d-major, transposed)
    float* Qs1 = Qs0 + 2048;
    float* Ks0 = Qs1 + 2048;
    float* Ks1 = Ks0 + 2048;
    float* Vs  = Ks1 + 2048;          // [64][64]
    float* Ps0 = Vs + 4096;           // [64][SST]  ([key][qrow])
    float* Ps1 = Ps0 + 64 * SST;
    float* msh0 = Ps1 + 64 * SST;
    float* msh1 = msh0 + 64;
    float* lsh0 = msh1 + 64;
    float* lsh1 = lsh0 + 64;
    float* ash0 = lsh1 + 64;
    float* ash1 = ash0 + 64;

    const int tid = threadIdx.x;
    const int tx = tid & 15, ty = tid >> 4;
    const int warp = tid >> 5, lane = tid & 31;

    const int blk = blockIdx.x;
    const int qt = blk & 31;
    const int h  = (blk >> 5) & 7;
    const int b  = blk >> 8;
    const int q0row = qt * 64;

    const float* qb0 = q_s + ((size_t)((b * 16 + 2 * h)     * TT + q0row)) * 32;
    const float* qb1 = q_s + ((size_t)((b * 16 + 2 * h + 1) * TT + q0row)) * 32;
    const float* kb0 = k_s + ((size_t)((b * 16 + 2 * h)     * TT)) * 32;
    const float* kb1 = k_s + ((size_t)((b * 16 + 2 * h + 1) * TT)) * 32;
    const float* vb  = v_s + ((size_t)((b * 8 + h) * TT)) * 64;

    // Load Q tiles, transposed to [d][row]
#pragma unroll
    for (int it = 0; it < 2; it++) {
        int f = tid + it * 256;
        int row = f >> 3, dq = (f & 7) * 4;
        float4 a0 = *(const float4*)&qb0[row * 32 + dq];
        float4 a1 = *(const float4*)&qb1[row * 32 + dq];
        Qs0[(dq + 0) * 64 + row] = a0.x; Qs0[(dq + 1) * 64 + row] = a0.y;
        Qs0[(dq + 2) * 64 + row] = a0.z; Qs0[(dq + 3) * 64 + row] = a0.w;
        Qs1[(dq + 0) * 64 + row] = a1.x; Qs1[(dq + 1) * 64 + row] = a1.y;
        Qs1[(dq + 2) * 64 + row] = a1.z; Qs1[(dq + 3) * 64 + row] = a1.w;
    }
    if (tid < 64) { msh0[tid] = -1e30f; msh1[tid] = -1e30f; lsh0[tid] = 0.f; lsh1[tid] = 0.f; }

    float O0[4][4] = {}, O1[4][4] = {};
    __syncthreads();

    for (int k0 = 0; k0 < TT; k0 += 64) {
        // Load K tiles (transposed) and V tile
#pragma unroll
        for (int it = 0; it < 2; it++) {
            int f = tid + it * 256;
            int row = f >> 3, dq = (f & 7) * 4;
            float4 a0 = *(const float4*)&kb0[(size_t)(k0 + row) * 32 + dq];
            float4 a1 = *(const float4*)&kb1[(size_t)(k0 + row) * 32 + dq];
            Ks0[(dq + 0) * 64 + row] = a0.x; Ks0[(dq + 1) * 64 + row] = a0.y;
            Ks0[(dq + 2) * 64 + row] = a0.z; Ks0[(dq + 3) * 64 + row] = a0.w;
            Ks1[(dq + 0) * 64 + row] = a1.x; Ks1[(dq + 1) * 64 + row] = a1.y;
            Ks1[(dq + 2) * 64 + row] = a1.z; Ks1[(dq + 3) * 64 + row] = a1.w;
        }
#pragma unroll
        for (int it = 0; it < 4; it++) {
            int f = tid + it * 256;
            int row = f >> 4, cq = (f & 15) * 4;
            *(float4*)&Vs[row * 64 + cq] = *(const float4*)&vb[(size_t)(k0 + row) * 64 + cq];
        }
        __syncthreads();

        // S = Q @ K^T  (both streams), 4x4 microtiles
        float S0[4][4] = {}, S1[4][4] = {};
#pragma unroll 8
        for (int d = 0; d < 32; d++) {
            float a0[4], a1[4], b0[4], b1[4];
            *(float4*)a0 = *(const float4*)&Qs0[d * 64 + ty * 4];
            *(float4*)a1 = *(const float4*)&Qs1[d * 64 + ty * 4];
            *(float4*)b0 = *(const float4*)&Ks0[d * 64 + tx * 4];
            *(float4*)b1 = *(const float4*)&Ks1[d * 64 + tx * 4];
#pragma unroll
            for (int i = 0; i < 4; i++)
#pragma unroll
                for (int j = 0; j < 4; j++) {
                    S0[i][j] = fmaf(a0[i], b0[j], S0[i][j]);
                    S1[i][j] = fmaf(a1[i], b1[j], S1[i][j]);
                }
        }
        // Stage S into shared ([key][qrow]) for row reductions
#pragma unroll
        for (int i = 0; i < 4; i++)
#pragma unroll
            for (int j = 0; j < 4; j++) {
                Ps0[(tx * 4 + j) * SST + ty * 4 + i] = S0[i][j];
                Ps1[(tx * 4 + j) * SST + ty * 4 + i] = S1[i][j];
            }
        __syncthreads();

        // Per-row max -> m_new, alpha  (warp w owns rows w*8..w*8+7)
#pragma unroll
        for (int k = 0; k < 8; k++) {
            int r = warp * 8 + k;
            float t0 = fmaxf(Ps0[lane * SST + r], Ps0[(lane + 32) * SST + r]);
            float t1 = fmaxf(Ps1[lane * SST + r], Ps1[(lane + 32) * SST + r]);
#pragma unroll
            for (int o = 16; o; o >>= 1) {
                t0 = fmaxf(t0, __shfl_xor_sync(0xffffffffu, t0, o));
                t1 = fmaxf(t1, __shfl_xor_sync(0xffffffffu, t1, o));
            }
            if (lane == 0) {
                float mo = msh0[r], mn = fmaxf(mo, t0);
                ash0[r] = __expf(mo - mn); msh0[r] = mn;
                mo = msh1[r]; mn = fmaxf(mo, t1);
                ash1[r] = __expf(mo - mn); msh1[r] = mn;
            }
        }
        __syncthreads();

        // Rescale O, compute P = exp(S - m_new), stage P
        float rm0[4], rm1[4];
#pragma unroll
        for (int i = 0; i < 4; i++) {
            int r = ty * 4 + i;
            rm0[i] = msh0[r]; rm1[i] = msh1[r];
            float a0v = ash0[r], a1v = ash1[r];
#pragma unroll
            for (int j = 0; j < 4; j++) { O0[i][j] *= a0v; O1[i][j] *= a1v; }
        }
#pragma unroll
        for (int i = 0; i < 4; i++)
#pragma unroll
            for (int j = 0; j < 4; j++) {
                Ps0[(tx * 4 + j) * SST + ty * 4 + i] = __expf(S0[i][j] - rm0[i]);
                Ps1[(tx * 4 + j) * SST + ty * 4 + i] = __expf(S1[i][j] - rm1[i]);
            }
        __syncthreads();

        // Row sums -> l update
#pragma unroll
        for (int k = 0; k < 8; k++) {
            int r = warp * 8 + k;
            float s0 = Ps0[lane * SST + r] + Ps0[(lane + 32) * SST + r];
            float s1 = Ps1[lane * SST + r] + Ps1[(lane + 32) * SST + r];
#pragma unroll
            for (int o = 16; o; o >>= 1) {
                s0 += __shfl_xor_sync(0xffffffffu, s0, o);
                s1 += __shfl_xor_sync(0xffffffffu, s1, o);
            }
            if (lane == 0) {
                lsh0[r] = lsh0[r] * ash0[r] + s0;
                lsh1[r] = lsh1[r] * ash1[r] + s1;
            }
        }

        // O += P @ V  (V shared between streams)
#pragma unroll 8
        for (int kk = 0; kk < 64; kk++) {
            float a0[4], a1[4], bv[4];
            *(float4*)a0 = *(const float4*)&Ps0[kk * SST + ty * 4];
            *(float4*)a1 = *(const float4*)&Ps1[kk * SST + ty * 4];
            *(float4*)bv = *(const float4*)&Vs[kk * 64 + tx * 4];
#pragma unroll
            for (int i = 0; i < 4; i++)
#pragma unroll
                for (int j = 0; j < 4; j++) {
                    O0[i][j] = fmaf(a0[i], bv[j], O0[i][j]);
                    O1[i][j] = fmaf(a1[i], bv[j], O1[i][j]);
                }
        }
        __syncthreads();
    }

    // Final: diff of normalized streams, RMS-norm, gamma, scale, store
    float lam = g_lam;
    float il0[4], il1[4];
#pragma unroll
    for (int i = 0; i < 4; i++) {
        int r = ty * 4 + i;
        il0[i] = 1.f / lsh0[r];
        il1[i] = lam / lsh1[r];
    }
#pragma unroll
    for (int i = 0; i < 4; i++)
#pragma unroll
        for (int j = 0; j < 4; j++)
            Vs[(ty * 4 + i) * 64 + tx * 4 + j] = O0[i][j] * il0[i] - O1[i][j] * il1[i];
    __syncthreads();

#pragma unroll
    for (int k = 0; k < 8; k++) {
        int r = warp * 8 + k;
        float x0 = Vs[r * 64 + lane], x1 = Vs[r * 64 + lane + 32];
        float ss = x0 * x0 + x1 * x1;
#pragma unroll
        for (int o = 16; o; o >>= 1) ss += __shfl_xor_sync(0xffffffffu, ss, o);
        float rms = sqrtf(ss * (1.f / 64.f));
        float sc = ONE_MINUS_LI / (rms + 1e-8f);
        float* op = attn_s + ((size_t)(b * TT + q0row + r)) * 512 + h * 64;
        op[lane]      = x0 * sc * gamma[lane];
        op[lane + 32] = x1 * sc * gamma[lane + 32];
    }
}

// ---------------------------------------------------------------------------
// Kernel 4: output GEMM.  out[4096,1024] = attn_s[4096,512] @ Wout[512,1024]
// ---------------------------------------------------------------------------
__global__ __launch_bounds__(256) void gemm_out_kernel(
    const float* __restrict__ Wout, float* __restrict__ C)
{
    const int n0 = blockIdx.x * 128;
    const int m0 = blockIdx.y * 128;
    __shared__ float As[16][128];
    __shared__ float Bs[16][128];
    float acc[8][8] = {};
    const int tid = threadIdx.x;
    const int tx = tid & 15, ty = tid >> 4;

    for (int kt = 0; kt < 512; kt += 16) {
#pragma unroll
        for (int it = 0; it < 2; it++) {
            int f = tid + it * 256;
            int row = f >> 2, kq = (f & 3) * 4;
            float4 a = *(const float4*)&attn_s[(size_t)(m0 + row) * 512 + kt + kq];
            As[kq + 0][row] = a.x; As[kq + 1][row] = a.y;
            As[kq + 2][row] = a.z; As[kq + 3][row] = a.w;
        }
#pragma unroll
        for (int it = 0; it < 2; it++) {
            int f = tid + it * 256;
            int row = f >> 5, cq = (f & 31) * 4;
            *(float4*)&Bs[row][cq] = *(const float4*)&Wout[(size_t)(kt + row) * 1024 + n0 + cq];
        }
        __syncthreads();
#pragma unroll
        for (int k = 0; k < 16; k++) {
            float a[8], bb[8];
            *(float4*)&a[0] = *(const float4*)&As[k][ty * 8];
            *(float4*)&a[4] = *(const float4*)&As[k][ty * 8 + 4];
            *(float4*)&bb[0] = *(const float4*)&Bs[k][tx * 8];
            *(float4*)&bb[4] = *(const float4*)&Bs[k][tx * 8 + 4];
#pragma unroll
            for (int i = 0; i < 8; i++)
#pragma unroll
                for (int j = 0; j < 8; j++)
                    acc[i][j] = fmaf(a[i], bb[j], acc[i][j]);
        }
        __syncthreads();
    }
#pragma unroll
    for (int i = 0; i < 8; i++) {
        float* cp = C + (size_t)(m0 + ty * 8 + i) * 1024 + n0 + tx * 8;
        *(float4*)cp       = *(float4*)&acc[i][0];
        *(float4*)(cp + 4) = *(float4*)&acc[i][4];
    }
}

// ---------------------------------------------------------------------------
extern "C" void kernel_launch(void* const* d_in, const int* in_sizes, int n_in,
                              void* d_out, int out_size)
{
    const float* x    = (const float*)d_in[0];
    const float* Wq   = (const float*)d_in[1];
    const float* Wkv  = (const float*)d_in[2];
    const float* Wout = (const float*)d_in[3];
    const float* lq1  = (const float*)d_in[4];
    const float* lk1  = (const float*)d_in[5];
    const float* lq2  = (const float*)d_in[6];
    const float* lk2  = (const float*)d_in[7];
    const float* gamma = (const float*)d_in[8];
    float* out = (float*)d_out;

    cudaFuncSetAttribute(attn_kernel, cudaFuncAttributeMaxDynamicSharedMemorySize,
                         ATTN_SMEM_BYTES);

    gemm_qkv_kernel<<<dim3(12, 32), 256>>>(x, Wq, Wkv);
    lam_kernel<<<1, 32>>>(lq1, lk1, lq2, lk2);
    attn_kernel<<<BB * HH * (TT / 64), 256, ATTN_SMEM_BYTES>>>(gamma);
    gemm_out_kernel<<<dim3(8, 32), 256>>>(Wout, out);
}

// round 5
// speedup vs baseline: 1.8053x; 1.8053x over previous
#include <cuda_runtime.h>
#include <cuda_bf16.h>
#include <math.h>
#include <stdint.h>

// Problem constants
#define BB 2
#define TT 2048
#define HH 8
#define LAMBDA_INIT 0.355509067591f
#define ONE_MINUS_LI 0.644490932409f
#define Q_SCALE 0.17677669529663687f  // 32^-0.5

// ---------------------------------------------------------------------------
// Device scratch
// ---------------------------------------------------------------------------
__device__ float q_s[(size_t)BB * 16 * TT * 32];   // [B,2H,T,D]
__device__ float k_s[(size_t)BB * 16 * TT * 32];   // [B,2H,T,D]
__device__ float v_s[(size_t)BB * 8 * TT * 64];    // [B,H,T,2D]
__device__ float g_lam;

// split-bf16 operands
__device__ __nv_bfloat16 x_hi[(size_t)4096 * 1024];
__device__ __nv_bfloat16 x_lo[(size_t)4096 * 1024];
__device__ __nv_bfloat16 wt_hi[(size_t)1536 * 1024];   // [Wq|Wkv]^T  [N,K]
__device__ __nv_bfloat16 wt_lo[(size_t)1536 * 1024];
__device__ __nv_bfloat16 wot_hi[(size_t)1024 * 512];   // Wout^T [N,K]
__device__ __nv_bfloat16 wot_lo[(size_t)1024 * 512];
__device__ __nv_bfloat16 attn_hi[(size_t)4096 * 512];  // attention output, split
__device__ __nv_bfloat16 attn_lo[(size_t)4096 * 512];

// ---------------------------------------------------------------------------
// MMA helpers (sm_80+ instructions, valid on plain sm_103 target)
// ---------------------------------------------------------------------------
__device__ __forceinline__ uint32_t smem_u32(const void* p) {
    uint32_t a;
    asm("{ .reg .u64 t; cvta.to.shared.u64 t, %1; cvt.u32.u64 %0, t; }"
        : "=r"(a) : "l"(p));
    return a;
}
__device__ __forceinline__ void ldsm_x4(uint32_t r[4], uint32_t addr) {
    asm volatile("ldmatrix.sync.aligned.m8n8.x4.shared.b16 {%0,%1,%2,%3}, [%4];"
                 : "=r"(r[0]), "=r"(r[1]), "=r"(r[2]), "=r"(r[3]) : "r"(addr));
}
__device__ __forceinline__ void mma16816(float c[4], const uint32_t a[4],
                                         const uint32_t b[2]) {
    asm volatile(
        "mma.sync.aligned.m16n8k16.row.col.f32.bf16.bf16.f32 "
        "{%0,%1,%2,%3}, {%4,%5,%6,%7}, {%8,%9}, {%0,%1,%2,%3};"
        : "+f"(c[0]), "+f"(c[1]), "+f"(c[2]), "+f"(c[3])
        : "r"(a[0]), "r"(a[1]), "r"(a[2]), "r"(a[3]), "r"(b[0]), "r"(b[1]));
}

// ---------------------------------------------------------------------------
// Split conversion kernels
// ---------------------------------------------------------------------------
__global__ __launch_bounds__(256) void convx_kernel(const float* __restrict__ src)
{
    int i = blockIdx.x * 256 + threadIdx.x;
    float4 v = ((const float4*)src)[i];
    float vv[4] = {v.x, v.y, v.z, v.w};
    __nv_bfloat16 h[4], l[4];
#pragma unroll
    for (int j = 0; j < 4; j++) {
        h[j] = __float2bfloat16(vv[j]);
        l[j] = __float2bfloat16(vv[j] - __bfloat162float(h[j]));
    }
    ((uint2*)x_hi)[i] = *(uint2*)h;
    ((uint2*)x_lo)[i] = *(uint2*)l;
}

// Transpose [Wq | Wkv] -> wt[1536, 1024]
__global__ __launch_bounds__(256) void convw_kernel(const float* __restrict__ Wq,
                                                    const float* __restrict__ Wkv)
{
    __shared__ float t[32][33];
    int n0 = blockIdx.x * 32, k0 = blockIdx.y * 32;
    int tx = threadIdx.x & 31, ty = threadIdx.x >> 5;
#pragma unroll
    for (int s = 0; s < 4; s++) {
        int k = k0 + ty + 8 * s;
        int n = n0 + tx;
        float v = (n0 < 512) ? Wq[(size_t)k * 512 + n] : Wkv[(size_t)k * 1024 + (n - 512)];
        t[ty + 8 * s][tx] = v;
    }
    __syncthreads();
#pragma unroll
    for (int s = 0; s < 4; s++) {
        int n = n0 + ty + 8 * s;
        int k = k0 + tx;
        float v = t[tx][ty + 8 * s];
        __nv_bfloat16 h = __float2bfloat16(v);
        wt_hi[(size_t)n * 1024 + k] = h;
        wt_lo[(size_t)n * 1024 + k] = __float2bfloat16(v - __bfloat162float(h));
    }
}

// Transpose Wout [512,1024] -> wot[1024, 512]
__global__ __launch_bounds__(256) void convwout_kernel(const float* __restrict__ Wout)
{
    __shared__ float t[32][33];
    int n0 = blockIdx.x * 32, k0 = blockIdx.y * 32;
    int tx = threadIdx.x & 31, ty = threadIdx.x >> 5;
#pragma unroll
    for (int s = 0; s < 4; s++)
        t[ty + 8 * s][tx] = Wout[(size_t)(k0 + ty + 8 * s) * 1024 + n0 + tx];
    __syncthreads();
#pragma unroll
    for (int s = 0; s < 4; s++) {
        int n = n0 + ty + 8 * s;
        int k = k0 + tx;
        float v = t[tx][ty + 8 * s];
        __nv_bfloat16 h = __float2bfloat16(v);
        wot_hi[(size_t)n * 512 + k] = h;
        wot_lo[(size_t)n * 512 + k] = __float2bfloat16(v - __bfloat162float(h));
    }
}

// ---------------------------------------------------------------------------
// lambda scalar
// ---------------------------------------------------------------------------
__global__ void lam_kernel(const float* __restrict__ lq1, const float* __restrict__ lk1,
                           const float* __restrict__ lq2, const float* __restrict__ lk2)
{
    int lane = threadIdx.x;
    float p1 = lq1[lane] * lk1[lane];
    float p2 = lq2[lane] * lk2[lane];
#pragma unroll
    for (int o = 16; o; o >>= 1) {
        p1 += __shfl_xor_sync(0xffffffffu, p1, o);
        p2 += __shfl_xor_sync(0xffffffffu, p2, o);
    }
    if (lane == 0) g_lam = expf(p1) - expf(p2) + LAMBDA_INIT;
}

// ---------------------------------------------------------------------------
// HMMA split-bf16 GEMM core. D[128,128] = A[128,K] @ B[128,K]^T
// 8 warps in 2x4 grid, warp tile 64x32, BK=32, smem row stride 40 bf16.
// 3 terms per k-step: Ahi*Bhi + Alo*Bhi + Ahi*Blo (fp32 accum).
// ---------------------------------------------------------------------------
#define LDT 40            // padded bf16 row stride (80B -> conflict-free ldmatrix)
#define TSZ (128 * LDT)   // one tile, elements

template<int KTOT>
__device__ __forceinline__ void hgemm_core(
    float acc[4][4][4], __nv_bfloat16* sm,
    const __nv_bfloat16* __restrict__ ahi, const __nv_bfloat16* __restrict__ alo,
    const __nv_bfloat16* __restrict__ bhi, const __nv_bfloat16* __restrict__ blo,
    int lda, int ldb)
{
    const int tid = threadIdx.x;
    const int lane = tid & 31, warp = tid >> 5;
    const int wr = warp >> 2, wc = warp & 3;

    const uint32_t sa = smem_u32(sm);

    // precompute ldmatrix lane addresses (byte offsets within a tile)
    const int a_row = (lane & 15);
    const int a_col = (lane >> 4) * 8;
    const int b_row = ((lane >> 3) & 1) * 8 + (lane & 7);
    const int b_col = (lane >> 4) * 8;

    for (int kt = 0; kt < KTOT; kt += 32) {
        // ---- global -> smem: 4 tiles of [128 x 32] bf16 -------------------
#pragma unroll
        for (int it = 0; it < 2; it++) {
            int idx = tid + it * 256;            // 0..511
            int row = idx >> 2, colc = (idx & 3) * 8;
            uint32_t so = (uint32_t)(row * LDT + colc);
            *(uint4*)(sm + so)           = *(const uint4*)(ahi + (size_t)row * lda + kt + colc);
            *(uint4*)(sm + TSZ + so)     = *(const uint4*)(alo + (size_t)row * lda + kt + colc);
            *(uint4*)(sm + 2 * TSZ + so) = *(const uint4*)(bhi + (size_t)row * ldb + kt + colc);
            *(uint4*)(sm + 3 * TSZ + so) = *(const uint4*)(blo + (size_t)row * ldb + kt + colc);
        }
        __syncthreads();

        // ---- fragments + MMAs --------------------------------------------
#pragma unroll
        for (int ks = 0; ks < 2; ks++) {
            uint32_t af[4][4], lf[4][4], bf[4][2], qf[4][2];
#pragma unroll
            for (int mt = 0; mt < 4; mt++) {
                int row = wr * 64 + mt * 16 + a_row;
                uint32_t ad = sa + (uint32_t)(row * LDT + ks * 16 + a_col) * 2;
                ldsm_x4(af[mt], ad);
                ldsm_x4(lf[mt], ad + TSZ * 2);
            }
#pragma unroll
            for (int np = 0; np < 2; np++) {
                int row = wc * 32 + np * 16 + b_row;
                uint32_t bd = sa + 2 * TSZ * 2 + (uint32_t)(row * LDT + ks * 16 + b_col) * 2;
                uint32_t t[4];
                ldsm_x4(t, bd);
                bf[np * 2][0] = t[0]; bf[np * 2][1] = t[2];
                bf[np * 2 + 1][0] = t[1]; bf[np * 2 + 1][1] = t[3];
                ldsm_x4(t, bd + TSZ * 2);
                qf[np * 2][0] = t[0]; qf[np * 2][1] = t[2];
                qf[np * 2 + 1][0] = t[1]; qf[np * 2 + 1][1] = t[3];
            }
#pragma unroll
            for (int mt = 0; mt < 4; mt++)
#pragma unroll
                for (int nt = 0; nt < 4; nt++) {
                    mma16816(acc[mt][nt], af[mt], bf[nt]);
                    mma16816(acc[mt][nt], lf[mt], bf[nt]);
                    mma16816(acc[mt][nt], af[mt], qf[nt]);
                }
        }
        __syncthreads();
    }
}

// QKV: C[4096,1536] = X @ [Wq|Wkv]; scatter into q_s/k_s/v_s
__global__ __launch_bounds__(256) void gemm_qkv_tc(void)
{
    __shared__ __nv_bfloat16 sm[4 * TSZ];
    const int n0 = blockIdx.x * 128;
    const int m0 = blockIdx.y * 128;

    float acc[4][4][4] = {};
    hgemm_core<1024>(acc, sm,
                     x_hi + (size_t)m0 * 1024, x_lo + (size_t)m0 * 1024,
                     wt_hi + (size_t)n0 * 1024, wt_lo + (size_t)n0 * 1024,
                     1024, 1024);

    const int tid = threadIdx.x;
    const int lane = tid & 31, warp = tid >> 5;
    const int wr = warp >> 2, wc = warp & 3;

#pragma unroll
    for (int mt = 0; mt < 4; mt++)
#pragma unroll
        for (int nt = 0; nt < 4; nt++) {
            int r = wr * 64 + mt * 16 + (lane >> 2);
            int c = wc * 32 + nt * 8 + (lane & 3) * 2;
            int n = n0 + c;
#pragma unroll
            for (int half = 0; half < 2; half++) {
                int m = m0 + r + half * 8;
                int b = m >> 11, t = m & 2047;
                float2 v = make_float2(acc[mt][nt][half * 2], acc[mt][nt][half * 2 + 1]);
                if (n0 < 512) {
                    int hh = n >> 5, d = n & 31;
                    v.x *= Q_SCALE; v.y *= Q_SCALE;
                    *(float2*)&q_s[(((size_t)(b * 16 + hh)) * TT + t) * 32 + d] = v;
                } else if (n0 < 1024) {
                    int cc = n - 512;
                    int hh = cc >> 5, d = cc & 31;
                    *(float2*)&k_s[(((size_t)(b * 16 + hh)) * TT + t) * 32 + d] = v;
                } else {
                    int cc = n - 1024;
                    int hd = cc >> 6, dd = cc & 63;
                    *(float2*)&v_s[(((size_t)(b * 8 + hd)) * TT + t) * 64 + dd] = v;
                }
            }
        }
}

// OUT: out[4096,1024] = attn[4096,512] @ Wout[512,1024]
__global__ __launch_bounds__(256) void gemm_out_tc(float* __restrict__ C)
{
    __shared__ __nv_bfloat16 sm[4 * TSZ];
    const int n0 = blockIdx.x * 128;
    const int m0 = blockIdx.y * 128;

    float acc[4][4][4] = {};
    hgemm_core<512>(acc, sm,
                    attn_hi + (size_t)m0 * 512, attn_lo + (size_t)m0 * 512,
                    wot_hi + (size_t)n0 * 512, wot_lo + (size_t)n0 * 512,
                    512, 512);

    const int tid = threadIdx.x;
    const int lane = tid & 31, warp = tid >> 5;
    const int wr = warp >> 2, wc = warp & 3;

#pragma unroll
    for (int mt = 0; mt < 4; mt++)
#pragma unroll
        for (int nt = 0; nt < 4; nt++) {
            int r = wr * 64 + mt * 16 + (lane >> 2);
            int c = wc * 32 + nt * 8 + (lane & 3) * 2;
#pragma unroll
            for (int half = 0; half < 2; half++) {
                float2 v = make_float2(acc[mt][nt][half * 2], acc[mt][nt][half * 2 + 1]);
                *(float2*)&C[(size_t)(m0 + r + half * 8) * 1024 + n0 + c] = v;
            }
        }
}

// ---------------------------------------------------------------------------
// Differential flash attention (fp32), register softmax, epilogue emits split bf16
// ---------------------------------------------------------------------------
#define SST 68
#define ATTN_SMEM_BYTES ((4 * 2048 + 4096 + 2 * 64 * SST) * 4)

__global__ __launch_bounds__(256, 2) void attn_kernel(const float* __restrict__ gamma)
{
    extern __shared__ float smf[];
    float* Qs0 = smf;                 // [32][64] (d-major)
    float* Qs1 = Qs0 + 2048;
    float* Ks0 = Qs1 + 2048;
    float* Ks1 = Ks0 + 2048;
    float* Vs  = Ks1 + 2048;          // [64][64]
    float* Ps0 = Vs + 4096;           // [qrow][SST]
    float* Ps1 = Ps0 + 64 * SST;

    const int tid = threadIdx.x;
    const int tx = tid & 15, ty = tid >> 4;
    const int warp = tid >> 5, lane = tid & 31;

    const int blk = blockIdx.x;
    const int qt = blk & 31;
    const int h  = (blk >> 5) & 7;
    const int b  = blk >> 8;
    const int q0row = qt * 64;

    const float* qb0 = q_s + ((size_t)((b * 16 + 2 * h)     * TT + q0row)) * 32;
    const float* qb1 = q_s + ((size_t)((b * 16 + 2 * h + 1) * TT + q0row)) * 32;
    const float* kb0 = k_s + ((size_t)((b * 16 + 2 * h)     * TT)) * 32;
    const float* kb1 = k_s + ((size_t)((b * 16 + 2 * h + 1) * TT)) * 32;
    const float* vb  = v_s + ((size_t)((b * 8 + h) * TT)) * 64;

#pragma unroll
    for (int it = 0; it < 2; it++) {
        int f = tid + it * 256;
        int row = f >> 3, dq = (f & 7) * 4;
        float4 a0 = *(const float4*)&qb0[row * 32 + dq];
        float4 a1 = *(const float4*)&qb1[row * 32 + dq];
        Qs0[(dq + 0) * 64 + row] = a0.x; Qs0[(dq + 1) * 64 + row] = a0.y;
        Qs0[(dq + 2) * 64 + row] = a0.z; Qs0[(dq + 3) * 64 + row] = a0.w;
        Qs1[(dq + 0) * 64 + row] = a1.x; Qs1[(dq + 1) * 64 + row] = a1.y;
        Qs1[(dq + 2) * 64 + row] = a1.z; Qs1[(dq + 3) * 64 + row] = a1.w;
    }

    float O0[4][4] = {}, O1[4][4] = {};
    float m0r[4], m1r[4], l0r[4], l1r[4];
#pragma unroll
    for (int i = 0; i < 4; i++) { m0r[i] = -1e30f; m1r[i] = -1e30f; l0r[i] = 0.f; l1r[i] = 0.f; }
    __syncthreads();

    for (int k0 = 0; k0 < TT; k0 += 64) {
#pragma unroll
        for (int it = 0; it < 2; it++) {
            int f = tid + it * 256;
            int row = f >> 3, dq = (f & 7) * 4;
            float4 a0 = *(const float4*)&kb0[(size_t)(k0 + row) * 32 + dq];
            float4 a1 = *(const float4*)&kb1[(size_t)(k0 + row) * 32 + dq];
            Ks0[(dq + 0) * 64 + row] = a0.x; Ks0[(dq + 1) * 64 + row] = a0.y;
            Ks0[(dq + 2) * 64 + row] = a0.z; Ks0[(dq + 3) * 64 + row] = a0.w;
            Ks1[(dq + 0) * 64 + row] = a1.x; Ks1[(dq + 1) * 64 + row] = a1.y;
            Ks1[(dq + 2) * 64 + row] = a1.z; Ks1[(dq + 3) * 64 + row] = a1.w;
        }
#pragma unroll
        for (int it = 0; it < 4; it++) {
            int f = tid + it * 256;
            int row = f >> 4, cq = (f & 15) * 4;
            *(float4*)&Vs[row * 64 + cq] = *(const float4*)&vb[(size_t)(k0 + row) * 64 + cq];
        }
        __syncthreads();

        float S0[4][4] = {}, S1[4][4] = {};
#pragma unroll 8
        for (int d = 0; d < 32; d++) {
            float a0[4], a1[4], b0[4], b1[4];
            *(float4*)a0 = *(const float4*)&Qs0[d * 64 + ty * 4];
            *(float4*)a1 = *(const float4*)&Qs1[d * 64 + ty * 4];
            *(float4*)b0 = *(const float4*)&Ks0[d * 64 + tx * 4];
            *(float4*)b1 = *(const float4*)&Ks1[d * 64 + tx * 4];
#pragma unroll
            for (int i = 0; i < 4; i++)
#pragma unroll
                for (int j = 0; j < 4; j++) {
                    S0[i][j] = fmaf(a0[i], b0[j], S0[i][j]);
                    S1[i][j] = fmaf(a1[i], b1[j], S1[i][j]);
                }
        }

        // Register softmax (row owners = 16-lane group sharing ty)
#pragma unroll
        for (int i = 0; i < 4; i++) {
            float mx0 = fmaxf(fmaxf(S0[i][0], S0[i][1]), fmaxf(S0[i][2], S0[i][3]));
            float mx1 = fmaxf(fmaxf(S1[i][0], S1[i][1]), fmaxf(S1[i][2], S1[i][3]));
#pragma unroll
            for (int o = 8; o; o >>= 1) {
                mx0 = fmaxf(mx0, __shfl_xor_sync(0xffffffffu, mx0, o));
                mx1 = fmaxf(mx1, __shfl_xor_sync(0xffffffffu, mx1, o));
            }
            float mn0 = fmaxf(m0r[i], mx0);
            float mn1 = fmaxf(m1r[i], mx1);
            float al0 = __expf(m0r[i] - mn0);
            float al1 = __expf(m1r[i] - mn1);
            m0r[i] = mn0; m1r[i] = mn1;
            float s0 = 0.f, s1 = 0.f;
#pragma unroll
            for (int j = 0; j < 4; j++) {
                float p0 = __expf(S0[i][j] - mn0);
                float p1 = __expf(S1[i][j] - mn1);
                S0[i][j] = p0; S1[i][j] = p1;
                s0 += p0; s1 += p1;
                O0[i][j] *= al0; O1[i][j] *= al1;
            }
#pragma unroll
            for (int o = 8; o; o >>= 1) {
                s0 += __shfl_xor_sync(0xffffffffu, s0, o);
                s1 += __shfl_xor_sync(0xffffffffu, s1, o);
            }
            l0r[i] = l0r[i] * al0 + s0;
            l1r[i] = l1r[i] * al1 + s1;
            *(float4*)&Ps0[(ty * 4 + i) * SST + tx * 4] = *(float4*)S0[i];
            *(float4*)&Ps1[(ty * 4 + i) * SST + tx * 4] = *(float4*)S1[i];
        }
        __syncthreads();

        // O += P @ V
#pragma unroll 4
        for (int kk0 = 0; kk0 < 64; kk0 += 4) {
            float pa0[4][4], pa1[4][4], va[4][4];
#pragma unroll
            for (int r = 0; r < 4; r++)
                *(float4*)va[r] = *(const float4*)&Vs[(kk0 + r) * 64 + tx * 4];
#pragma unroll
            for (int i = 0; i < 4; i++) {
                *(float4*)pa0[i] = *(const float4*)&Ps0[(ty * 4 + i) * SST + kk0];
                *(float4*)pa1[i] = *(const float4*)&Ps1[(ty * 4 + i) * SST + kk0];
            }
#pragma unroll
            for (int i = 0; i < 4; i++)
#pragma unroll
                for (int r = 0; r < 4; r++)
#pragma unroll
                    for (int j = 0; j < 4; j++) {
                        O0[i][j] = fmaf(pa0[i][r], va[r][j], O0[i][j]);
                        O1[i][j] = fmaf(pa1[i][r], va[r][j], O1[i][j]);
                    }
        }
        __syncthreads();
    }

    float lam = g_lam;
#pragma unroll
    for (int i = 0; i < 4; i++) {
        float il0 = 1.f / l0r[i];
        float il1 = lam / l1r[i];
#pragma unroll
        for (int j = 0; j < 4; j++)
            Vs[(ty * 4 + i) * 64 + tx * 4 + j] = O0[i][j] * il0 - O1[i][j] * il1;
    }
    __syncthreads();

#pragma unroll
    for (int k = 0; k < 8; k++) {
        int r = warp * 8 + k;
        float x0 = Vs[r * 64 + lane], x1 = Vs[r * 64 + lane + 32];
        float ss = x0 * x0 + x1 * x1;
#pragma unroll
        for (int o = 16; o; o >>= 1) ss += __shfl_xor_sync(0xffffffffu, ss, o);
        float rms = sqrtf(ss * (1.f / 64.f));
        float sc = ONE_MINUS_LI / (rms + 1e-8f);
        size_t base = ((size_t)(b * TT + q0row + r)) * 512 + h * 64;
        float v0 = x0 * sc * gamma[lane];
        float v1 = x1 * sc * gamma[lane + 32];
        __nv_bfloat16 h0 = __float2bfloat16(v0);
        __nv_bfloat16 h1 = __float2bfloat16(v1);
        attn_hi[base + lane]      = h0;
        attn_lo[base + lane]      = __float2bfloat16(v0 - __bfloat162float(h0));
        attn_hi[base + lane + 32] = h1;
        attn_lo[base + lane + 32] = __float2bfloat16(v1 - __bfloat162float(h1));
    }
}

// ---------------------------------------------------------------------------
extern "C" void kernel_launch(void* const* d_in, const int* in_sizes, int n_in,
                              void* d_out, int out_size)
{
    const float* x    = (const float*)d_in[0];
    const float* Wq   = (const float*)d_in[1];
    const float* Wkv  = (const float*)d_in[2];
    const float* Wout = (const float*)d_in[3];
    const float* lq1  = (const float*)d_in[4];
    const float* lk1  = (const float*)d_in[5];
    const float* lq2  = (const float*)d_in[6];
    const float* lk2  = (const float*)d_in[7];
    const float* gamma = (const float*)d_in[8];
    float* out = (float*)d_out;

    cudaFuncSetAttribute(attn_kernel, cudaFuncAttributeMaxDynamicSharedMemorySize,
                         ATTN_SMEM_BYTES);

    convx_kernel<<<4096, 256>>>(x);
    convw_kernel<<<dim3(48, 32), 256>>>(Wq, Wkv);
    convwout_kernel<<<dim3(32, 16), 256>>>(Wout);
    lam_kernel<<<1, 32>>>(lq1, lk1, lq2, lk2);

    gemm_qkv_tc<<<dim3(12, 32), 256>>>();
    attn_kernel<<<BB * HH * (TT / 64), 256, ATTN_SMEM_BYTES>>>(gamma);
    gemm_out_tc<<<dim3(8, 32), 256>>>(out);
}

// round 6
// speedup vs baseline: 3.2957x; 1.8256x over previous
#include <cuda_runtime.h>
#include <cuda_bf16.h>
#include <math.h>
#include <stdint.h>

// Problem constants
#define BB 2
#define TT 2048
#define HH 8
#define LAMBDA_INIT 0.355509067591f
#define ONE_MINUS_LI 0.644490932409f
#define Q_SCALE 0.17677669529663687f  // 32^-0.5

// ---------------------------------------------------------------------------
// Device scratch
// ---------------------------------------------------------------------------
__device__ float v_s[(size_t)BB * 8 * TT * 64];    // [B,H,T,2D] float (pre-transpose)
__device__ float g_lam;

// split-bf16 operands
__device__ __nv_bfloat16 x_hi[(size_t)4096 * 1024];
__device__ __nv_bfloat16 x_lo[(size_t)4096 * 1024];
__device__ __nv_bfloat16 wt_hi[(size_t)1536 * 1024];   // [Wq|Wkv]^T  [N,K]
__device__ __nv_bfloat16 wt_lo[(size_t)1536 * 1024];
__device__ __nv_bfloat16 wot_hi[(size_t)1024 * 512];   // Wout^T [N,K]
__device__ __nv_bfloat16 wot_lo[(size_t)1024 * 512];
__device__ __nv_bfloat16 attn_hi[(size_t)4096 * 512];  // attention output, split
__device__ __nv_bfloat16 attn_lo[(size_t)4096 * 512];

// attention operands (split bf16, written by QKV epilogue / transpose kernel)
__device__ __nv_bfloat16 q_hi[(size_t)BB * 16 * TT * 32];  // [B,2H,T,D]
__device__ __nv_bfloat16 q_lo[(size_t)BB * 16 * TT * 32];
__device__ __nv_bfloat16 k_hi[(size_t)BB * 16 * TT * 32];
__device__ __nv_bfloat16 k_lo[(size_t)BB * 16 * TT * 32];
__device__ __nv_bfloat16 vt_hi[(size_t)BB * 8 * 64 * TT]; // [B,H,2D,T]  (V^T)
__device__ __nv_bfloat16 vt_lo[(size_t)BB * 8 * 64 * TT];

// ---------------------------------------------------------------------------
// MMA helpers (sm_80+ instructions, valid on plain sm_103 target)
// ---------------------------------------------------------------------------
__device__ __forceinline__ uint32_t smem_u32(const void* p) {
    uint32_t a;
    asm("{ .reg .u64 t; cvta.to.shared.u64 t, %1; cvt.u32.u64 %0, t; }"
        : "=r"(a) : "l"(p));
    return a;
}
__device__ __forceinline__ void ldsm_x4(uint32_t r[4], uint32_t addr) {
    asm volatile("ldmatrix.sync.aligned.m8n8.x4.shared.b16 {%0,%1,%2,%3}, [%4];"
                 : "=r"(r[0]), "=r"(r[1]), "=r"(r[2]), "=r"(r[3]) : "r"(addr));
}
__device__ __forceinline__ void mma16816(float c[4], const uint32_t a[4],
                                         const uint32_t b[2]) {
    asm volatile(
        "mma.sync.aligned.m16n8k16.row.col.f32.bf16.bf16.f32 "
        "{%0,%1,%2,%3}, {%4,%5,%6,%7}, {%8,%9}, {%0,%1,%2,%3};"
        : "+f"(c[0]), "+f"(c[1]), "+f"(c[2]), "+f"(c[3])
        : "r"(a[0]), "r"(a[1]), "r"(a[2]), "r"(a[3]), "r"(b[0]), "r"(b[1]));
}

// ---------------------------------------------------------------------------
// Split conversion kernels
// ---------------------------------------------------------------------------
__global__ __launch_bounds__(256) void convx_kernel(const float* __restrict__ src)
{
    int i = blockIdx.x * 256 + threadIdx.x;
    float4 v = ((const float4*)src)[i];
    float vv[4] = {v.x, v.y, v.z, v.w};
    __nv_bfloat16 h[4], l[4];
#pragma unroll
    for (int j = 0; j < 4; j++) {
        h[j] = __float2bfloat16(vv[j]);
        l[j] = __float2bfloat16(vv[j] - __bfloat162float(h[j]));
    }
    ((uint2*)x_hi)[i] = *(uint2*)h;
    ((uint2*)x_lo)[i] = *(uint2*)l;
}

__global__ __launch_bounds__(256) void convw_kernel(const float* __restrict__ Wq,
                                                    const float* __restrict__ Wkv)
{
    __shared__ float t[32][33];
    int n0 = blockIdx.x * 32, k0 = blockIdx.y * 32;
    int tx = threadIdx.x & 31, ty = threadIdx.x >> 5;
#pragma unroll
    for (int s = 0; s < 4; s++) {
        int k = k0 + ty + 8 * s;
        int n = n0 + tx;
        float v = (n0 < 512) ? Wq[(size_t)k * 512 + n] : Wkv[(size_t)k * 1024 + (n - 512)];
        t[ty + 8 * s][tx] = v;
    }
    __syncthreads();
#pragma unroll
    for (int s = 0; s < 4; s++) {
        int n = n0 + ty + 8 * s;
        int k = k0 + tx;
        float v = t[tx][ty + 8 * s];
        __nv_bfloat16 h = __float2bfloat16(v);
        wt_hi[(size_t)n * 1024 + k] = h;
        wt_lo[(size_t)n * 1024 + k] = __float2bfloat16(v - __bfloat162float(h));
    }
}

__global__ __launch_bounds__(256) void convwout_kernel(const float* __restrict__ Wout)
{
    __shared__ float t[32][33];
    int n0 = blockIdx.x * 32, k0 = blockIdx.y * 32;
    int tx = threadIdx.x & 31, ty = threadIdx.x >> 5;
#pragma unroll
    for (int s = 0; s < 4; s++)
        t[ty + 8 * s][tx] = Wout[(size_t)(k0 + ty + 8 * s) * 1024 + n0 + tx];
    __syncthreads();
#pragma unroll
    for (int s = 0; s < 4; s++) {
        int n = n0 + ty + 8 * s;
        int k = k0 + tx;
        float v = t[tx][ty + 8 * s];
        __nv_bfloat16 h = __float2bfloat16(v);
        wot_hi[(size_t)n * 512 + k] = h;
        wot_lo[(size_t)n * 512 + k] = __float2bfloat16(v - __bfloat162float(h));
    }
}

// V transpose + split:  v_s [B,H,T,64] f32  ->  vt_hi/vt_lo [B,H,64,T] bf16
__global__ __launch_bounds__(256) void vtrans_kernel(void)
{
    __shared__ float t[32][33];
    int t0 = blockIdx.x * 32, d0 = blockIdx.y * 32, bh = blockIdx.z;
    int tx = threadIdx.x & 31, ty = threadIdx.x >> 5;
    const float* src = v_s + (size_t)bh * TT * 64;
#pragma unroll
    for (int s = 0; s < 4; s++)
        t[ty + 8 * s][tx] = src[(size_t)(t0 + ty + 8 * s) * 64 + d0 + tx];
    __syncthreads();
#pragma unroll
    for (int s = 0; s < 4; s++) {
        int d = d0 + ty + 8 * s;
        float v = t[tx][ty + 8 * s];
        __nv_bfloat16 h = __float2bfloat16(v);
        size_t o = ((size_t)bh * 64 + d) * TT + t0 + tx;
        vt_hi[o] = h;
        vt_lo[o] = __float2bfloat16(v - __bfloat162float(h));
    }
}

// ---------------------------------------------------------------------------
// lambda scalar
// ---------------------------------------------------------------------------
__global__ void lam_kernel(const float* __restrict__ lq1, const float* __restrict__ lk1,
                           const float* __restrict__ lq2, const float* __restrict__ lk2)
{
    int lane = threadIdx.x;
    float p1 = lq1[lane] * lk1[lane];
    float p2 = lq2[lane] * lk2[lane];
#pragma unroll
    for (int o = 16; o; o >>= 1) {
        p1 += __shfl_xor_sync(0xffffffffu, p1, o);
        p2 += __shfl_xor_sync(0xffffffffu, p2, o);
    }
    if (lane == 0) g_lam = expf(p1) - expf(p2) + LAMBDA_INIT;
}

// ---------------------------------------------------------------------------
// HMMA split-bf16 GEMM core (same as R5, validated)
// ---------------------------------------------------------------------------
#define LDT 40
#define TSZ (128 * LDT)

template<int KTOT>
__device__ __forceinline__ void hgemm_core(
    float acc[4][4][4], __nv_bfloat16* sm,
    const __nv_bfloat16* __restrict__ ahi, const __nv_bfloat16* __restrict__ alo,
    const __nv_bfloat16* __restrict__ bhi, const __nv_bfloat16* __restrict__ blo,
    int lda, int ldb)
{
    const int tid = threadIdx.x;
    const int lane = tid & 31, warp = tid >> 5;
    const int wr = warp >> 2, wc = warp & 3;
    const uint32_t sa = smem_u32(sm);

    const int a_row = (lane & 15);
    const int a_col = (lane >> 4) * 8;
    const int b_row = ((lane >> 3) & 1) * 8 + (lane & 7);
    const int b_col = (lane >> 4) * 8;

    for (int kt = 0; kt < KTOT; kt += 32) {
#pragma unroll
        for (int it = 0; it < 2; it++) {
            int idx = tid + it * 256;
            int row = idx >> 2, colc = (idx & 3) * 8;
            uint32_t so = (uint32_t)(row * LDT + colc);
            *(uint4*)(sm + so)           = *(const uint4*)(ahi + (size_t)row * lda + kt + colc);
            *(uint4*)(sm + TSZ + so)     = *(const uint4*)(alo + (size_t)row * lda + kt + colc);
            *(uint4*)(sm + 2 * TSZ + so) = *(const uint4*)(bhi + (size_t)row * ldb + kt + colc);
            *(uint4*)(sm + 3 * TSZ + so) = *(const uint4*)(blo + (size_t)row * ldb + kt + colc);
        }
        __syncthreads();

#pragma unroll
        for (int ks = 0; ks < 2; ks++) {
            uint32_t af[4][4], lf[4][4], bf[4][2], qf[4][2];
#pragma unroll
            for (int mt = 0; mt < 4; mt++) {
                int row = wr * 64 + mt * 16 + a_row;
                uint32_t ad = sa + (uint32_t)(row * LDT + ks * 16 + a_col) * 2;
                ldsm_x4(af[mt], ad);
                ldsm_x4(lf[mt], ad + TSZ * 2);
            }
#pragma unroll
            for (int np = 0; np < 2; np++) {
                int row = wc * 32 + np * 16 + b_row;
                uint32_t bd = sa + 2 * TSZ * 2 + (uint32_t)(row * LDT + ks * 16 + b_col) * 2;
                uint32_t t[4];
                ldsm_x4(t, bd);
                bf[np * 2][0] = t[0]; bf[np * 2][1] = t[2];
                bf[np * 2 + 1][0] = t[1]; bf[np * 2 + 1][1] = t[3];
                ldsm_x4(t, bd + TSZ * 2);
                qf[np * 2][0] = t[0]; qf[np * 2][1] = t[2];
                qf[np * 2 + 1][0] = t[1]; qf[np * 2 + 1][1] = t[3];
            }
#pragma unroll
            for (int mt = 0; mt < 4; mt++)
#pragma unroll
                for (int nt = 0; nt < 4; nt++) {
                    mma16816(acc[mt][nt], af[mt], bf[nt]);
                    mma16816(acc[mt][nt], lf[mt], bf[nt]);
                    mma16816(acc[mt][nt], af[mt], qf[nt]);
                }
        }
        __syncthreads();
    }
}

// QKV: scatter into q_hi/lo (scaled), k_hi/lo, v_s
__global__ __launch_bounds__(256) void gemm_qkv_tc(void)
{
    __shared__ __nv_bfloat16 sm[4 * TSZ];
    const int n0 = blockIdx.x * 128;
    const int m0 = blockIdx.y * 128;

    float acc[4][4][4] = {};
    hgemm_core<1024>(acc, sm,
                     x_hi + (size_t)m0 * 1024, x_lo + (size_t)m0 * 1024,
                     wt_hi + (size_t)n0 * 1024, wt_lo + (size_t)n0 * 1024,
                     1024, 1024);

    const int tid = threadIdx.x;
    const int lane = tid & 31, warp = tid >> 5;
    const int wr = warp >> 2, wc = warp & 3;

#pragma unroll
    for (int mt = 0; mt < 4; mt++)
#pragma unroll
        for (int nt = 0; nt < 4; nt++) {
            int r = wr * 64 + mt * 16 + (lane >> 2);
            int c = wc * 32 + nt * 8 + (lane & 3) * 2;
            int n = n0 + c;
#pragma unroll
            for (int half = 0; half < 2; half++) {
                int m = m0 + r + half * 8;
                int b = m >> 11, t = m & 2047;
                float vx = acc[mt][nt][half * 2], vy = acc[mt][nt][half * 2 + 1];
                if (n0 < 512) {
                    int hh = n >> 5, d = n & 31;
                    vx *= Q_SCALE; vy *= Q_SCALE;
                    __nv_bfloat162 h2 = __floats2bfloat162_rn(vx, vy);
                    float2 hf = __bfloat1622float2(h2);
                    __nv_bfloat162 l2 = __floats2bfloat162_rn(vx - hf.x, vy - hf.y);
                    size_t o = (((size_t)(b * 16 + hh)) * TT + t) * 32 + d;
                    *(__nv_bfloat162*)&q_hi[o] = h2;
                    *(__nv_bfloat162*)&q_lo[o] = l2;
                } else if (n0 < 1024) {
                    int cc = n - 512;
                    int hh = cc >> 5, d = cc & 31;
                    __nv_bfloat162 h2 = __floats2bfloat162_rn(vx, vy);
                    float2 hf = __bfloat1622float2(h2);
                    __nv_bfloat162 l2 = __floats2bfloat162_rn(vx - hf.x, vy - hf.y);
                    size_t o = (((size_t)(b * 16 + hh)) * TT + t) * 32 + d;
                    *(__nv_bfloat162*)&k_hi[o] = h2;
                    *(__nv_bfloat162*)&k_lo[o] = l2;
                } else {
                    int cc = n - 1024;
                    int hd = cc >> 6, dd = cc & 63;
                    *(float2*)&v_s[(((size_t)(b * 8 + hd)) * TT + t) * 64 + dd] =
                        make_float2(vx, vy);
                }
            }
        }
}

// OUT: out[4096,1024] = attn[4096,512] @ Wout[512,1024]
__global__ __launch_bounds__(256) void gemm_out_tc(float* __restrict__ C)
{
    __shared__ __nv_bfloat16 sm[4 * TSZ];
    const int n0 = blockIdx.x * 128;
    const int m0 = blockIdx.y * 128;

    float acc[4][4][4] = {};
    hgemm_core<512>(acc, sm,
                    attn_hi + (size_t)m0 * 512, attn_lo + (size_t)m0 * 512,
                    wot_hi + (size_t)n0 * 512, wot_lo + (size_t)n0 * 512,
                    512, 512);

    const int tid = threadIdx.x;
    const int lane = tid & 31, warp = tid >> 5;
    const int wr = warp >> 2, wc = warp & 3;

#pragma unroll
    for (int mt = 0; mt < 4; mt++)
#pragma unroll
        for (int nt = 0; nt < 4; nt++) {
            int r = wr * 64 + mt * 16 + (lane >> 2);
            int c = wc * 32 + nt * 8 + (lane & 3) * 2;
#pragma unroll
            for (int half = 0; half < 2; half++) {
                float2 v = make_float2(acc[mt][nt][half * 2], acc[mt][nt][half * 2 + 1]);
                *(float2*)&C[(size_t)(m0 + r + half * 8) * 1024 + n0 + c] = v;
            }
        }
}

// ---------------------------------------------------------------------------
// HMMA differential flash attention.
// Block: 128 q-rows for one (b,h). Warps 0-3: head 2h, warps 4-7: head 2h+1.
// Smem (bf16 elems): Q tiles [4 x 128x40] | K tiles [4 x 64x40] | Vt [2 x 64x72]
// ---------------------------------------------------------------------------
#define ALDK 40
#define ALDV 72
#define AQ_OFF 0          // 4 * 5120
#define AK_OFF 20480      // 4 * 2560
#define AV_OFF 30720      // 2 * 4608
#define ATT_SMEM_ELEMS (AV_OFF + 2 * 4608)
#define ATT_SMEM_BYTES (ATT_SMEM_ELEMS * 2)
#define BUF_LD 66

__global__ __launch_bounds__(256, 1) void attn2_kernel(const float* __restrict__ gamma)
{
    extern __shared__ __nv_bfloat16 sb[];
    const int tid = threadIdx.x, lane = tid & 31, warp = tid >> 5;
    const int s = warp >> 2, wq = warp & 3;
    const int qt = blockIdx.x, h = blockIdx.y, b = blockIdx.z;
    const int q0 = qt * 128;

    const int a_row = (lane & 15);
    const int a_col = (lane >> 4) * 8;
    const int b_row = ((lane >> 3) & 1) * 8 + (lane & 7);
    const int b_col = (lane >> 4) * 8;

    // ---- load Q (4 tiles: hi/lo x 2 streams) ------------------------------
    {
        const __nv_bfloat16* qsrc[4] = {
            q_hi + ((size_t)((b * 16 + 2 * h) * TT) + q0) * 32,
            q_lo + ((size_t)((b * 16 + 2 * h) * TT) + q0) * 32,
            q_hi + ((size_t)((b * 16 + 2 * h + 1) * TT) + q0) * 32,
            q_lo + ((size_t)((b * 16 + 2 * h + 1) * TT) + q0) * 32};
#pragma unroll
        for (int a = 0; a < 4; a++)
#pragma unroll
            for (int i = 0; i < 2; i++) {
                int idx = tid + i * 256;
                int row = idx >> 2, c = idx & 3;
                *(uint4*)&sb[AQ_OFF + a * 5120 + row * ALDK + c * 8] =
                    *(const uint4*)&qsrc[a][(size_t)row * 32 + c * 8];
            }
    }

    const __nv_bfloat16* ksrc[4] = {
        k_hi + (size_t)((b * 16 + 2 * h) * TT) * 32,
        k_lo + (size_t)((b * 16 + 2 * h) * TT) * 32,
        k_hi + (size_t)((b * 16 + 2 * h + 1) * TT) * 32,
        k_lo + (size_t)((b * 16 + 2 * h + 1) * TT) * 32};
    const __nv_bfloat16* vsrc[2] = {
        vt_hi + ((size_t)(b * 8 + h) * 64) * TT,
        vt_lo + ((size_t)(b * 8 + h) * 64) * TT};

    const uint32_t sbase = smem_u32(sb);
    const uint32_t qbase = sbase + (AQ_OFF + s * 2 * 5120) * 2;
    const uint32_t kbase = sbase + (AK_OFF + s * 2 * 2560) * 2;
    const uint32_t vbase = sbase + AV_OFF * 2;

    float O[2][8][4] = {};
    float m[4], l[4];
#pragma unroll
    for (int i = 0; i < 4; i++) { m[i] = -1e30f; l[i] = 0.f; }

    for (int k0g = 0; k0g < TT; k0g += 64) {
        // ---- load K tiles + Vt tiles --------------------------------------
#pragma unroll
        for (int a = 0; a < 4; a++) {
            int row = tid >> 2, c = tid & 3;
            *(uint4*)&sb[AK_OFF + a * 2560 + row * ALDK + c * 8] =
                *(const uint4*)&ksrc[a][(size_t)(k0g + row) * 32 + c * 8];
        }
#pragma unroll
        for (int p = 0; p < 2; p++)
#pragma unroll
            for (int i = 0; i < 2; i++) {
                int idx = tid + i * 256;
                int row = idx >> 3, c = idx & 7;
                *(uint4*)&sb[AV_OFF + p * 4608 + row * ALDV + c * 8] =
                    *(const uint4*)&vsrc[p][(size_t)row * TT + k0g + c * 8];
            }
        __syncthreads();

        // ---- S = Q K^T (split 3-term) -------------------------------------
        float S[2][8][4] = {};
#pragma unroll
        for (int ks = 0; ks < 2; ks++) {
            uint32_t ah[2][4], al[2][4], bh[8][2], bl[8][2];
#pragma unroll
            for (int mt = 0; mt < 2; mt++) {
                uint32_t ad = qbase +
                    (uint32_t)((wq * 32 + mt * 16 + a_row) * ALDK + ks * 16 + a_col) * 2;
                ldsm_x4(ah[mt], ad);
                ldsm_x4(al[mt], ad + 5120 * 2);
            }
#pragma unroll
            for (int np = 0; np < 4; np++) {
                uint32_t bd = kbase +
                    (uint32_t)((np * 16 + b_row) * ALDK + ks * 16 + b_col) * 2;
                uint32_t t[4];
                ldsm_x4(t, bd);
                bh[np * 2][0] = t[0]; bh[np * 2][1] = t[2];
                bh[np * 2 + 1][0] = t[1]; bh[np * 2 + 1][1] = t[3];
                ldsm_x4(t, bd + 2560 * 2);
                bl[np * 2][0] = t[0]; bl[np * 2][1] = t[2];
                bl[np * 2 + 1][0] = t[1]; bl[np * 2 + 1][1] = t[3];
            }
#pragma unroll
            for (int mt = 0; mt < 2; mt++)
#pragma unroll
                for (int nt = 0; nt < 8; nt++) {
                    mma16816(S[mt][nt], ah[mt], bh[nt]);
                    mma16816(S[mt][nt], al[mt], bh[nt]);
                    mma16816(S[mt][nt], ah[mt], bl[nt]);
                }
        }

        // ---- register softmax (rows in quad lanes) ------------------------
#pragma unroll
        for (int mt = 0; mt < 2; mt++)
#pragma unroll
            for (int half = 0; half < 2; half++) {
                const int idx = mt * 2 + half;
                float mx = -1e30f;
#pragma unroll
                for (int nt = 0; nt < 8; nt++)
                    mx = fmaxf(mx, fmaxf(S[mt][nt][half * 2], S[mt][nt][half * 2 + 1]));
                mx = fmaxf(mx, __shfl_xor_sync(0xffffffffu, mx, 1));
                mx = fmaxf(mx, __shfl_xor_sync(0xffffffffu, mx, 2));
                float mn = fmaxf(m[idx], mx);
                float al = __expf(m[idx] - mn);
                m[idx] = mn;
                float sum = 0.f;
#pragma unroll
                for (int nt = 0; nt < 8; nt++) {
                    float p0 = __expf(S[mt][nt][half * 2] - mn);
                    float p1 = __expf(S[mt][nt][half * 2 + 1] - mn);
                    S[mt][nt][half * 2] = p0; S[mt][nt][half * 2 + 1] = p1;
                    sum += p0 + p1;
                    O[mt][nt][half * 2] *= al; O[mt][nt][half * 2 + 1] *= al;
                }
                sum += __shfl_xor_sync(0xffffffffu, sum, 1);
                sum += __shfl_xor_sync(0xffffffffu, sum, 2);
                l[idx] = l[idx] * al + sum;
            }

        // ---- O += P V  (P in registers, split 3-term) ---------------------
#pragma unroll
        for (int ks = 0; ks < 4; ks++) {
            uint32_t ph[2][4], pl[2][4], vh[8][2], vl[8][2];
#pragma unroll
            for (int mt = 0; mt < 2; mt++) {
#pragma unroll
                for (int j = 0; j < 2; j++) {       // j=0 -> tile 2ks (a0,a1); j=1 -> 2ks+1 (a2,a3)
                    float p0 = S[mt][2 * ks + j][0], p1 = S[mt][2 * ks + j][1];
                    float p2 = S[mt][2 * ks + j][2], p3 = S[mt][2 * ks + j][3];
                    __nv_bfloat162 h01 = __floats2bfloat162_rn(p0, p1);
                    __nv_bfloat162 h23 = __floats2bfloat162_rn(p2, p3);
                    float2 f01 = __bfloat1622float2(h01);
                    float2 f23 = __bfloat1622float2(h23);
                    __nv_bfloat162 l01 = __floats2bfloat162_rn(p0 - f01.x, p1 - f01.y);
                    __nv_bfloat162 l23 = __floats2bfloat162_rn(p2 - f23.x, p3 - f23.y);
                    ph[mt][j * 2]     = *(uint32_t*)&h01;
                    ph[mt][j * 2 + 1] = *(uint32_t*)&h23;
                    pl[mt][j * 2]     = *(uint32_t*)&l01;
                    pl[mt][j * 2 + 1] = *(uint32_t*)&l23;
                }
            }
#pragma unroll
            for (int np = 0; np < 4; np++) {
                uint32_t bd = vbase +
                    (uint32_t)((np * 16 + b_row) * ALDV + ks * 16 + b_col) * 2;
                uint32_t t[4];
                ldsm_x4(t, bd);
                vh[np * 2][0] = t[0]; vh[np * 2][1] = t[2];
                vh[np * 2 + 1][0] = t[1]; vh[np * 2 + 1][1] = t[3];
                ldsm_x4(t, bd + 4608 * 2);
                vl[np * 2][0] = t[0]; vl[np * 2][1] = t[2];
                vl[np * 2 + 1][0] = t[1]; vl[np * 2 + 1][1] = t[3];
            }
#pragma unroll
            for (int mt = 0; mt < 2; mt++)
#pragma unroll
                for (int nt = 0; nt < 8; nt++) {
                    mma16816(O[mt][nt], ph[mt], vh[nt]);
                    mma16816(O[mt][nt], pl[mt], vh[nt]);
                    mma16816(O[mt][nt], ph[mt], vl[nt]);
                }
        }
        __syncthreads();
    }

    // ---- normalize streams -----------------------------------------------
    float lam = g_lam;
#pragma unroll
    for (int mt = 0; mt < 2; mt++)
#pragma unroll
        for (int half = 0; half < 2; half++) {
            const int idx = mt * 2 + half;
            float sc = (s == 0) ? (1.f / l[idx]) : (lam / l[idx]);
#pragma unroll
            for (int nt = 0; nt < 8; nt++) {
                O[mt][nt][half * 2] *= sc;
                O[mt][nt][half * 2 + 1] *= sc;
            }
        }

    // ---- combine streams, RMS-norm, write split-bf16 ----------------------
    float* buf = (float*)&sb[AK_OFF];   // 128 x BUF_LD floats (overlays K+V tiles)
    if (s == 1) {
#pragma unroll
        for (int mt = 0; mt < 2; mt++)
#pragma unroll
            for (int half = 0; half < 2; half++) {
                int row = wq * 32 + mt * 16 + (lane >> 2) + half * 8;
#pragma unroll
                for (int nt = 0; nt < 8; nt++) {
                    int col = nt * 8 + (lane & 3) * 2;
                    buf[row * BUF_LD + col]     = O[mt][nt][half * 2];
                    buf[row * BUF_LD + col + 1] = O[mt][nt][half * 2 + 1];
                }
            }
    }
    __syncthreads();
    if (s == 0) {
#pragma unroll
        for (int mt = 0; mt < 2; mt++)
#pragma unroll
            for (int half = 0; half < 2; half++) {
                int row = wq * 32 + mt * 16 + (lane >> 2) + half * 8;
                float d0[8], d1[8];
                float ss = 0.f;
#pragma unroll
                for (int nt = 0; nt < 8; nt++) {
                    int col = nt * 8 + (lane & 3) * 2;
                    d0[nt] = O[mt][nt][half * 2]     - buf[row * BUF_LD + col];
                    d1[nt] = O[mt][nt][half * 2 + 1] - buf[row * BUF_LD + col + 1];
                    ss += d0[nt] * d0[nt] + d1[nt] * d1[nt];
                }
                ss += __shfl_xor_sync(0xffffffffu, ss, 1);
                ss += __shfl_xor_sync(0xffffffffu, ss, 2);
                float rms = sqrtf(ss * (1.f / 64.f));
                float sc = ONE_MINUS_LI / (rms + 1e-8f);
                size_t gb = ((size_t)(b * TT + q0 + row)) * 512 + h * 64;
#pragma unroll
                for (int nt = 0; nt < 8; nt++) {
                    int col = nt * 8 + (lane & 3) * 2;
                    float v0 = d0[nt] * sc * __ldg(&gamma[col]);
                    float v1 = d1[nt] * sc * __ldg(&gamma[col + 1]);
                    __nv_bfloat162 h2 = __floats2bfloat162_rn(v0, v1);
                    float2 hf = __bfloat1622float2(h2);
                    __nv_bfloat162 l2 = __floats2bfloat162_rn(v0 - hf.x, v1 - hf.y);
                    *(__nv_bfloat162*)&attn_hi[gb + col] = h2;
                    *(__nv_bfloat162*)&attn_lo[gb + col] = l2;
                }
            }
    }
}

// ---------------------------------------------------------------------------
extern "C" void kernel_launch(void* const* d_in, const int* in_sizes, int n_in,
                              void* d_out, int out_size)
{
    const float* x    = (const float*)d_in[0];
    const float* Wq   = (const float*)d_in[1];
    const float* Wkv  = (const float*)d_in[2];
    const float* Wout = (const float*)d_in[3];
    const float* lq1  = (const float*)d_in[4];
    const float* lk1  = (const float*)d_in[5];
    const float* lq2  = (const float*)d_in[6];
    const float* lk2  = (const float*)d_in[7];
    const float* gamma = (const float*)d_in[8];
    float* out = (float*)d_out;

    cudaFuncSetAttribute(attn2_kernel, cudaFuncAttributeMaxDynamicSharedMemorySize,
                         ATT_SMEM_BYTES);

    convx_kernel<<<4096, 256>>>(x);
    convw_kernel<<<dim3(48, 32), 256>>>(Wq, Wkv);
    convwout_kernel<<<dim3(32, 16), 256>>>(Wout);
    lam_kernel<<<1, 32>>>(lq1, lk1, lq2, lk2);

    gemm_qkv_tc<<<dim3(12, 32), 256>>>();
    vtrans_kernel<<<dim3(64, 2, 16), 256>>>();
    attn2_kernel<<<dim3(16, 8, 2), 256, ATT_SMEM_BYTES>>>(gamma);
    gemm_out_tc<<<dim3(8, 32), 256>>>(out);
}

// round 8
// speedup vs baseline: 3.5739x; 1.0844x over previous
#include <cuda_runtime.h>
#include <cuda_bf16.h>
#include <math.h>
#include <stdint.h>

// Problem constants
#define BB 2
#define TT 2048
#define HH 8
#define LAMBDA_INIT 0.355509067591f
#define ONE_MINUS_LI 0.644490932409f
#define Q_SCALE 0.17677669529663687f  // 32^-0.5

// ---------------------------------------------------------------------------
// Device scratch
// ---------------------------------------------------------------------------
__device__ float v_s[(size_t)BB * 8 * TT * 64];    // [B,H,T,2D] float (pre-transpose)

__device__ __nv_bfloat16 x_hi[(size_t)4096 * 1024];
__device__ __nv_bfloat16 x_lo[(size_t)4096 * 1024];
__device__ __nv_bfloat16 wt_hi[(size_t)1536 * 1024];   // [Wq|Wkv]^T  [N,K]
__device__ __nv_bfloat16 wt_lo[(size_t)1536 * 1024];
__device__ __nv_bfloat16 wot_hi[(size_t)1024 * 512];   // Wout^T [N,K]
__device__ __nv_bfloat16 wot_lo[(size_t)1024 * 512];
__device__ __nv_bfloat16 attn_hi[(size_t)4096 * 512];
__device__ __nv_bfloat16 attn_lo[(size_t)4096 * 512];

__device__ __nv_bfloat16 q_hi[(size_t)BB * 16 * TT * 32];  // [B,2H,T,D]
__device__ __nv_bfloat16 q_lo[(size_t)BB * 16 * TT * 32];
__device__ __nv_bfloat16 k_hi[(size_t)BB * 16 * TT * 32];
__device__ __nv_bfloat16 k_lo[(size_t)BB * 16 * TT * 32];
__device__ __nv_bfloat16 vt_hi[(size_t)BB * 8 * 64 * TT]; // [B,H,2D,T]  (V^T)
__device__ __nv_bfloat16 vt_lo[(size_t)BB * 8 * 64 * TT];

// ---------------------------------------------------------------------------
// Helpers
// ---------------------------------------------------------------------------
__device__ __forceinline__ uint32_t smem_u32(const void* p) {
    uint32_t a;
    asm("{ .reg .u64 t; cvta.to.shared.u64 t, %1; cvt.u32.u64 %0, t; }"
        : "=r"(a) : "l"(p));
    return a;
}
__device__ __forceinline__ void ldsm_x4(uint32_t r[4], uint32_t addr) {
    asm volatile("ldmatrix.sync.aligned.m8n8.x4.shared.b16 {%0,%1,%2,%3}, [%4];"
                 : "=r"(r[0]), "=r"(r[1]), "=r"(r[2]), "=r"(r[3]) : "r"(addr));
}
__device__ __forceinline__ void mma16816(float c[4], const uint32_t a[4],
                                         const uint32_t b[2]) {
    asm volatile(
        "mma.sync.aligned.m16n8k16.row.col.f32.bf16.bf16.f32 "
        "{%0,%1,%2,%3}, {%4,%5,%6,%7}, {%8,%9}, {%0,%1,%2,%3};"
        : "+f"(c[0]), "+f"(c[1]), "+f"(c[2]), "+f"(c[3])
        : "r"(a[0]), "r"(a[1]), "r"(a[2]), "r"(a[3]), "r"(b[0]), "r"(b[1]));
}
__device__ __forceinline__ void cpa16(uint32_t s, const void* g) {
    asm volatile("cp.async.cg.shared.global [%0], [%1], 16;" :: "r"(s), "l"(g));
}
__device__ __forceinline__ void cpa_commit() {
    asm volatile("cp.async.commit_group;" ::: "memory");
}
template<int N> __device__ __forceinline__ void cpa_wait() {
    asm volatile("cp.async.wait_group %0;" :: "n"(N) : "memory");
}

// ---------------------------------------------------------------------------
// Split conversion kernels
// ---------------------------------------------------------------------------
__global__ __launch_bounds__(256) void convx_kernel(const float* __restrict__ src)
{
    int i = blockIdx.x * 256 + threadIdx.x;
    float4 v = ((const float4*)src)[i];
    float vv[4] = {v.x, v.y, v.z, v.w};
    __nv_bfloat16 h[4], l[4];
#pragma unroll
    for (int j = 0; j < 4; j++) {
        h[j] = __float2bfloat16(vv[j]);
        l[j] = __float2bfloat16(vv[j] - __bfloat162float(h[j]));
    }
    ((uint2*)x_hi)[i] = *(uint2*)h;
    ((uint2*)x_lo)[i] = *(uint2*)l;
}

__global__ __launch_bounds__(256) void convw_kernel(const float* __restrict__ Wq,
                                                    const float* __restrict__ Wkv)
{
    __shared__ float t[32][33];
    int n0 = blockIdx.x * 32, k0 = blockIdx.y * 32;
    int tx = threadIdx.x & 31, ty = threadIdx.x >> 5;
#pragma unroll
    for (int s = 0; s < 4; s++) {
        int k = k0 + ty + 8 * s;
        int n = n0 + tx;
        float v = (n0 < 512) ? Wq[(size_t)k * 512 + n] : Wkv[(size_t)k * 1024 + (n - 512)];
        t[ty + 8 * s][tx] = v;
    }
    __syncthreads();
#pragma unroll
    for (int s = 0; s < 4; s++) {
        int n = n0 + ty + 8 * s;
        int k = k0 + tx;
        float v = t[tx][ty + 8 * s];
        __nv_bfloat16 h = __float2bfloat16(v);
        wt_hi[(size_t)n * 1024 + k] = h;
        wt_lo[(size_t)n * 1024 + k] = __float2bfloat16(v - __bfloat162float(h));
    }
}

__global__ __launch_bounds__(256) void convwout_kernel(const float* __restrict__ Wout)
{
    __shared__ float t[32][33];
    int n0 = blockIdx.x * 32, k0 = blockIdx.y * 32;
    int tx = threadIdx.x & 31, ty = threadIdx.x >> 5;
#pragma unroll
    for (int s = 0; s < 4; s++)
        t[ty + 8 * s][tx] = Wout[(size_t)(k0 + ty + 8 * s) * 1024 + n0 + tx];
    __syncthreads();
#pragma unroll
    for (int s = 0; s < 4; s++) {
        int n = n0 + ty + 8 * s;
        int k = k0 + tx;
        float v = t[tx][ty + 8 * s];
        __nv_bfloat16 h = __float2bfloat16(v);
        wot_hi[(size_t)n * 512 + k] = h;
        wot_lo[(size_t)n * 512 + k] = __float2bfloat16(v - __bfloat162float(h));
    }
}

// V transpose + split:  v_s [B,H,T,64] f32  ->  vt_hi/vt_lo [B,H,64,T] bf16
__global__ __launch_bounds__(256) void vtrans_kernel(void)
{
    __shared__ float t[32][33];
    int t0 = blockIdx.x * 32, d0 = blockIdx.y * 32, bh = blockIdx.z;
    int tx = threadIdx.x & 31, ty = threadIdx.x >> 5;
    const float* src = v_s + (size_t)bh * TT * 64;
#pragma unroll
    for (int s = 0; s < 4; s++)
        t[ty + 8 * s][tx] = src[(size_t)(t0 + ty + 8 * s) * 64 + d0 + tx];
    __syncthreads();
#pragma unroll
    for (int s = 0; s < 4; s++) {
        int d = d0 + ty + 8 * s;
        float v = t[tx][ty + 8 * s];
        __nv_bfloat16 h = __float2bfloat16(v);
        size_t o = ((size_t)bh * 64 + d) * TT + t0 + tx;
        vt_hi[o] = h;
        vt_lo[o] = __float2bfloat16(v - __bfloat162float(h));
    }
}

// ---------------------------------------------------------------------------
// HMMA split-bf16 GEMM core with 2-stage cp.async pipeline.
// D[128,128] = A[128,K] @ B[128,K]^T, BK=32, 8 warps 2x4, 3-term split.
// ---------------------------------------------------------------------------
#define LDT 40
#define TSZ (128 * LDT)
#define GEMM_STAGE_B (4 * TSZ * 2)           // bytes per stage (4 tiles)
#define GEMM_SMEM_BYTES (2 * GEMM_STAGE_B)   // 81920

template<int KTOT>
__device__ __forceinline__ void hgemm_core(
    float acc[4][4][4], __nv_bfloat16* sm,
    const __nv_bfloat16* __restrict__ ahi, const __nv_bfloat16* __restrict__ alo,
    const __nv_bfloat16* __restrict__ bhi, const __nv_bfloat16* __restrict__ blo,
    int lda, int ldb)
{
    const int tid = threadIdx.x;
    const int lane = tid & 31, warp = tid >> 5;
    const int wr = warp >> 2, wc = warp & 3;
    const uint32_t sa = smem_u32(sm);

    const int a_row = (lane & 15);
    const int a_col = (lane >> 4) * 8;
    const int b_row = ((lane >> 3) & 1) * 8 + (lane & 7);
    const int b_col = (lane >> 4) * 8;

    const int ld_row = tid >> 2, ld_c = (tid & 3) * 8;         // idx 0..255
    const int ld_row2 = (tid + 256) >> 2, ld_c2 = ((tid + 256) & 3) * 8;

    auto issue = [&](int kt, int stg) {
        uint32_t sb = sa + stg * GEMM_STAGE_B;
        uint32_t so = (uint32_t)(ld_row * LDT + ld_c) * 2;
        cpa16(sb + so,                 ahi + (size_t)ld_row * lda + kt + ld_c);
        cpa16(sb + TSZ * 2 + so,       alo + (size_t)ld_row * lda + kt + ld_c);
        cpa16(sb + 2 * TSZ * 2 + so,   bhi + (size_t)ld_row * ldb + kt + ld_c);
        cpa16(sb + 3 * TSZ * 2 + so,   blo + (size_t)ld_row * ldb + kt + ld_c);
        so = (uint32_t)(ld_row2 * LDT + ld_c2) * 2;
        cpa16(sb + so,                 ahi + (size_t)ld_row2 * lda + kt + ld_c2);
        cpa16(sb + TSZ * 2 + so,       alo + (size_t)ld_row2 * lda + kt + ld_c2);
        cpa16(sb + 2 * TSZ * 2 + so,   bhi + (size_t)ld_row2 * ldb + kt + ld_c2);
        cpa16(sb + 3 * TSZ * 2 + so,   blo + (size_t)ld_row2 * ldb + kt + ld_c2);
        cpa_commit();
    };

    constexpr int NIT = KTOT / 32;
    issue(0, 0);

    for (int it = 0; it < NIT; it++) {
        if (it + 1 < NIT) { issue((it + 1) * 32, (it + 1) & 1); cpa_wait<1>(); }
        else              { cpa_wait<0>(); }
        __syncthreads();

        const uint32_t ss = sa + (it & 1) * GEMM_STAGE_B;
#pragma unroll
        for (int ks = 0; ks < 2; ks++) {
            uint32_t af[4][4], lf[4][4], bf[4][2], qf[4][2];
#pragma unroll
            for (int mt = 0; mt < 4; mt++) {
                int row = wr * 64 + mt * 16 + a_row;
                uint32_t ad = ss + (uint32_t)(row * LDT + ks * 16 + a_col) * 2;
                ldsm_x4(af[mt], ad);
                ldsm_x4(lf[mt], ad + TSZ * 2);
            }
#pragma unroll
            for (int np = 0; np < 2; np++) {
                int row = wc * 32 + np * 16 + b_row;
                uint32_t bd = ss + 2 * TSZ * 2 + (uint32_t)(row * LDT + ks * 16 + b_col) * 2;
                uint32_t t[4];
                ldsm_x4(t, bd);
                bf[np * 2][0] = t[0]; bf[np * 2][1] = t[2];
                bf[np * 2 + 1][0] = t[1]; bf[np * 2 + 1][1] = t[3];
                ldsm_x4(t, bd + TSZ * 2);
                qf[np * 2][0] = t[0]; qf[np * 2][1] = t[2];
                qf[np * 2 + 1][0] = t[1]; qf[np * 2 + 1][1] = t[3];
            }
#pragma unroll
            for (int mt = 0; mt < 4; mt++)
#pragma unroll
                for (int nt = 0; nt < 4; nt++) {
                    mma16816(acc[mt][nt], af[mt], bf[nt]);
                    mma16816(acc[mt][nt], lf[mt], bf[nt]);
                    mma16816(acc[mt][nt], af[mt], qf[nt]);
                }
        }
        __syncthreads();
    }
}

// QKV: scatter into q_hi/lo (scaled), k_hi/lo, v_s
__global__ __launch_bounds__(256) void gemm_qkv_tc(void)
{
    extern __shared__ __nv_bfloat16 smd[];
    const int n0 = blockIdx.x * 128;
    const int m0 = blockIdx.y * 128;

    float acc[4][4][4] = {};
    hgemm_core<1024>(acc, smd,
                     x_hi + (size_t)m0 * 1024, x_lo + (size_t)m0 * 1024,
                     wt_hi + (size_t)n0 * 1024, wt_lo + (size_t)n0 * 1024,
                     1024, 1024);

    const int tid = threadIdx.x;
    const int lane = tid & 31, warp = tid >> 5;
    const int wr = warp >> 2, wc = warp & 3;

#pragma unroll
    for (int mt = 0; mt < 4; mt++)
#pragma unroll
        for (int nt = 0; nt < 4; nt++) {
            int r = wr * 64 + mt * 16 + (lane >> 2);
            int c = wc * 32 + nt * 8 + (lane & 3) * 2;
            int n = n0 + c;
#pragma unroll
            for (int half = 0; half < 2; half++) {
                int m = m0 + r + half * 8;
                int b = m >> 11, t = m & 2047;
                float vx = acc[mt][nt][half * 2], vy = acc[mt][nt][half * 2 + 1];
                if (n0 < 512) {
                    int hh = n >> 5, d = n & 31;
                    vx *= Q_SCALE; vy *= Q_SCALE;
                    __nv_bfloat162 h2 = __floats2bfloat162_rn(vx, vy);
                    float2 hf = __bfloat1622float2(h2);
                    __nv_bfloat162 l2 = __floats2bfloat162_rn(vx - hf.x, vy - hf.y);
                    size_t o = (((size_t)(b * 16 + hh)) * TT + t) * 32 + d;
                    *(__nv_bfloat162*)&q_hi[o] = h2;
                    *(__nv_bfloat162*)&q_lo[o] = l2;
                } else if (n0 < 1024) {
                    int cc = n - 512;
                    int hh = cc >> 5, d = cc & 31;
                    __nv_bfloat162 h2 = __floats2bfloat162_rn(vx, vy);
                    float2 hf = __bfloat1622float2(h2);
                    __nv_bfloat162 l2 = __floats2bfloat162_rn(vx - hf.x, vy - hf.y);
                    size_t o = (((size_t)(b * 16 + hh)) * TT + t) * 32 + d;
                    *(__nv_bfloat162*)&k_hi[o] = h2;
                    *(__nv_bfloat162*)&k_lo[o] = l2;
                } else {
                    int cc = n - 1024;
                    int hd = cc >> 6, dd = cc & 63;
                    *(float2*)&v_s[(((size_t)(b * 8 + hd)) * TT + t) * 64 + dd] =
                        make_float2(vx, vy);
                }
            }
        }
}

// OUT: out[4096,1024] = attn[4096,512] @ Wout[512,1024]
__global__ __launch_bounds__(256) void gemm_out_tc(float* __restrict__ C)
{
    extern __shared__ __nv_bfloat16 smd[];
    const int n0 = blockIdx.x * 128;
    const int m0 = blockIdx.y * 128;

    float acc[4][4][4] = {};
    hgemm_core<512>(acc, smd,
                    attn_hi + (size_t)m0 * 512, attn_lo + (size_t)m0 * 512,
                    wot_hi + (size_t)n0 * 512, wot_lo + (size_t)n0 * 512,
                    512, 512);

    const int tid = threadIdx.x;
    const int lane = tid & 31, warp = tid >> 5;
    const int wr = warp >> 2, wc = warp & 3;

#pragma unroll
    for (int mt = 0; mt < 4; mt++)
#pragma unroll
        for (int nt = 0; nt < 4; nt++) {
            int r = wr * 64 + mt * 16 + (lane >> 2);
            int c = wc * 32 + nt * 8 + (lane & 3) * 2;
#pragma unroll
            for (int half = 0; half < 2; half++) {
                float2 v = make_float2(acc[mt][nt][half * 2], acc[mt][nt][half * 2 + 1]);
                *(float2*)&C[(size_t)(m0 + r + half * 8) * 1024 + n0 + c] = v;
            }
        }
}

// ---------------------------------------------------------------------------
// HMMA differential flash attention, 2-stage cp.async K/V pipeline.
// Block: 128 q-rows, one (b,h). Warps 0-3: head 2h, warps 4-7: head 2h+1.
// ---------------------------------------------------------------------------
#define ALDK 40
#define ALDV 72
#define AQ_ELEMS 20480                 // 4 x 128x40
#define AK_STAGE 10240                 // 4 x 64x40 per stage
#define AV_STAGE 9216                  // 2 x 64x72 per stage
#define AK_OFF(stg) (AQ_ELEMS + (stg) * AK_STAGE)
#define AV_OFF(stg) (AQ_ELEMS + 2 * AK_STAGE + (stg) * AV_STAGE)
#define ATT_SMEM_BYTES ((AQ_ELEMS + 2 * AK_STAGE + 2 * AV_STAGE) * 2)
#define BUF_LD 66

__global__ __launch_bounds__(256, 1) void attn2_kernel(
    const float* __restrict__ gamma,
    const float* __restrict__ lq1, const float* __restrict__ lk1,
    const float* __restrict__ lq2, const float* __restrict__ lk2)
{
    extern __shared__ __nv_bfloat16 sb[];
    __shared__ float s_lam;
    const int tid = threadIdx.x, lane = tid & 31, warp = tid >> 5;
    const int s = warp >> 2, wq = warp & 3;
    const int qt = blockIdx.x, h = blockIdx.y, b = blockIdx.z;
    const int q0 = qt * 128;

    // inline lambda (warp 0)
    if (warp == 0) {
        float p1 = lq1[lane] * lk1[lane];
        float p2 = lq2[lane] * lk2[lane];
#pragma unroll
        for (int o = 16; o; o >>= 1) {
            p1 += __shfl_xor_sync(0xffffffffu, p1, o);
            p2 += __shfl_xor_sync(0xffffffffu, p2, o);
        }
        if (lane == 0) s_lam = expf(p1) - expf(p2) + LAMBDA_INIT;
    }

    const int a_row = (lane & 15);
    const int a_col = (lane >> 4) * 8;
    const int b_row = ((lane >> 3) & 1) * 8 + (lane & 7);
    const int b_col = (lane >> 4) * 8;

    // ---- load Q (plain, once) --------------------------------------------
    {
        const __nv_bfloat16* qsrc[4] = {
            q_hi + ((size_t)((b * 16 + 2 * h) * TT) + q0) * 32,
            q_lo + ((size_t)((b * 16 + 2 * h) * TT) + q0) * 32,
            q_hi + ((size_t)((b * 16 + 2 * h + 1) * TT) + q0) * 32,
            q_lo + ((size_t)((b * 16 + 2 * h + 1) * TT) + q0) * 32};
#pragma unroll
        for (int a = 0; a < 4; a++)
#pragma unroll
            for (int i = 0; i < 2; i++) {
                int idx = tid + i * 256;
                int row = idx >> 2, c = idx & 3;
                *(uint4*)&sb[a * 5120 + row * ALDK + c * 8] =
                    *(const uint4*)&qsrc[a][(size_t)row * 32 + c * 8];
            }
    }

    const __nv_bfloat16* ksrc[4] = {
        k_hi + (size_t)((b * 16 + 2 * h) * TT) * 32,
        k_lo + (size_t)((b * 16 + 2 * h) * TT) * 32,
        k_hi + (size_t)((b * 16 + 2 * h + 1) * TT) * 32,
        k_lo + (size_t)((b * 16 + 2 * h + 1) * TT) * 32};
    const __nv_bfloat16* vsrc[2] = {
        vt_hi + ((size_t)(b * 8 + h) * 64) * TT,
        vt_lo + ((size_t)(b * 8 + h) * 64) * TT};

    const uint32_t sbase = smem_u32(sb);
    const uint32_t qbase = sbase + (s * 2 * 5120) * 2;

    auto issue_kv = [&](int k0g, int stg) {
        uint32_t kb = sbase + AK_OFF(stg) * 2;
        uint32_t vb = sbase + AV_OFF(stg) * 2;
        int row = tid >> 2, c = tid & 3;
#pragma unroll
        for (int a = 0; a < 4; a++)
            cpa16(kb + (uint32_t)(a * 2560 + row * ALDK + c * 8) * 2,
                  ksrc[a] + (size_t)(k0g + row) * 32 + c * 8);
#pragma unroll
        for (int p = 0; p < 2; p++)
#pragma unroll
            for (int i = 0; i < 2; i++) {
                int idx = tid + i * 256;
                int vrow = idx >> 3, vc = idx & 7;
                cpa16(vb + (uint32_t)(p * 4608 + vrow * ALDV + vc * 8) * 2,
                      vsrc[p] + (size_t)vrow * TT + k0g + vc * 8);
            }
        cpa_commit();
    };

    float O[2][8][4] = {};
    float m[4], l[4];
#pragma unroll
    for (int i = 0; i < 4; i++) { m[i] = -1e30f; l[i] = 0.f; }

    issue_kv(0, 0);

    for (int it = 0; it < TT / 64; it++) {
        if (it + 1 < TT / 64) { issue_kv((it + 1) * 64, (it + 1) & 1); cpa_wait<1>(); }
        else                  { cpa_wait<0>(); }
        __syncthreads();

        const int stg = it & 1;
        const uint32_t kbase = sbase + (AK_OFF(stg) + s * 2 * 2560) * 2;
        const uint32_t vbase = sbase + AV_OFF(stg) * 2;

        // ---- S = Q K^T (split 3-term) -------------------------------------
        float S[2][8][4] = {};
#pragma unroll
        for (int ks = 0; ks < 2; ks++) {
            uint32_t ah[2][4], al[2][4], bh[8][2], bl[8][2];
#pragma unroll
            for (int mt = 0; mt < 2; mt++) {
                uint32_t ad = qbase +
                    (uint32_t)((wq * 32 + mt * 16 + a_row) * ALDK + ks * 16 + a_col) * 2;
                ldsm_x4(ah[mt], ad);
                ldsm_x4(al[mt], ad + 5120 * 2);
            }
#pragma unroll
            for (int np = 0; np < 4; np++) {
                uint32_t bd = kbase +
                    (uint32_t)((np * 16 + b_row) * ALDK + ks * 16 + b_col) * 2;
                uint32_t t[4];
                ldsm_x4(t, bd);
                bh[np * 2][0] = t[0]; bh[np * 2][1] = t[2];
                bh[np * 2 + 1][0] = t[1]; bh[np * 2 + 1][1] = t[3];
                ldsm_x4(t, bd + 2560 * 2);
                bl[np * 2][0] = t[0]; bl[np * 2][1] = t[2];
                bl[np * 2 + 1][0] = t[1]; bl[np * 2 + 1][1] = t[3];
            }
#pragma unroll
            for (int mt = 0; mt < 2; mt++)
#pragma unroll
                for (int nt = 0; nt < 8; nt++) {
                    mma16816(S[mt][nt], ah[mt], bh[nt]);
                    mma16816(S[mt][nt], al[mt], bh[nt]);
                    mma16816(S[mt][nt], ah[mt], bl[nt]);
                }
        }

        // ---- register softmax ---------------------------------------------
#pragma unroll
        for (int mt = 0; mt < 2; mt++)
#pragma unroll
            for (int half = 0; half < 2; half++) {
                const int idx = mt * 2 + half;
                float mx = -1e30f;
#pragma unroll
                for (int nt = 0; nt < 8; nt++)
                    mx = fmaxf(mx, fmaxf(S[mt][nt][half * 2], S[mt][nt][half * 2 + 1]));
                mx = fmaxf(mx, __shfl_xor_sync(0xffffffffu, mx, 1));
                mx = fmaxf(mx, __shfl_xor_sync(0xffffffffu, mx, 2));
                float mn = fmaxf(m[idx], mx);
                float al = __expf(m[idx] - mn);
                m[idx] = mn;
                float sum = 0.f;
#pragma unroll
                for (int nt = 0; nt < 8; nt++) {
                    float p0 = __expf(S[mt][nt][half * 2] - mn);
                    float p1 = __expf(S[mt][nt][half * 2 + 1] - mn);
                    S[mt][nt][half * 2] = p0; S[mt][nt][half * 2 + 1] = p1;
                    sum += p0 + p1;
                    O[mt][nt][half * 2] *= al; O[mt][nt][half * 2 + 1] *= al;
                }
                sum += __shfl_xor_sync(0xffffffffu, sum, 1);
                sum += __shfl_xor_sync(0xffffffffu, sum, 2);
                l[idx] = l[idx] * al + sum;
            }

        // ---- O += P V  (P repacked in registers, split 3-term) ------------
#pragma unroll
        for (int ks = 0; ks < 4; ks++) {
            uint32_t ph[2][4], pl[2][4], vh[8][2], vl[8][2];
#pragma unroll
            for (int mt = 0; mt < 2; mt++) {
#pragma unroll
                for (int j = 0; j < 2; j++) {
                    float p0 = S[mt][2 * ks + j][0], p1 = S[mt][2 * ks + j][1];
                    float p2 = S[mt][2 * ks + j][2], p3 = S[mt][2 * ks + j][3];
                    __nv_bfloat162 h01 = __floats2bfloat162_rn(p0, p1);
                    __nv_bfloat162 h23 = __floats2bfloat162_rn(p2, p3);
                    float2 f01 = __bfloat1622float2(h01);
                    float2 f23 = __bfloat1622float2(h23);
                    __nv_bfloat162 l01 = __floats2bfloat162_rn(p0 - f01.x, p1 - f01.y);
                    __nv_bfloat162 l23 = __floats2bfloat162_rn(p2 - f23.x, p3 - f23.y);
                    ph[mt][j * 2]     = *(uint32_t*)&h01;
                    ph[mt][j * 2 + 1] = *(uint32_t*)&h23;
                    pl[mt][j * 2]     = *(uint32_t*)&l01;
                    pl[mt][j * 2 + 1] = *(uint32_t*)&l23;
                }
            }
#pragma unroll
            for (int np = 0; np < 4; np++) {
                uint32_t bd = vbase +
                    (uint32_t)((np * 16 + b_row) * ALDV + ks * 16 + b_col) * 2;
                uint32_t t[4];
                ldsm_x4(t, bd);
                vh[np * 2][0] = t[0]; vh[np * 2][1] = t[2];
                vh[np * 2 + 1][0] = t[1]; vh[np * 2 + 1][1] = t[3];
                ldsm_x4(t, bd + 4608 * 2);
                vl[np * 2][0] = t[0]; vl[np * 2][1] = t[2];
                vl[np * 2 + 1][0] = t[1]; vl[np * 2 + 1][1] = t[3];
            }
#pragma unroll
            for (int mt = 0; mt < 2; mt++)
#pragma unroll
                for (int nt = 0; nt < 8; nt++) {
                    mma16816(O[mt][nt], ph[mt], vh[nt]);
                    mma16816(O[mt][nt], pl[mt], vh[nt]);
                    mma16816(O[mt][nt], ph[mt], vl[nt]);
                }
        }
        __syncthreads();
    }

    // ---- normalize streams -----------------------------------------------
    float lam = s_lam;
#pragma unroll
    for (int mt = 0; mt < 2; mt++)
#pragma unroll
        for (int half = 0; half < 2; half++) {
            const int idx = mt * 2 + half;
            float sc = (s == 0) ? (1.f / l[idx]) : (lam / l[idx]);
#pragma unroll
            for (int nt = 0; nt < 8; nt++) {
                O[mt][nt][half * 2] *= sc;
                O[mt][nt][half * 2 + 1] *= sc;
            }
        }

    // ---- combine streams, RMS-norm, write split-bf16 ----------------------
    float* buf = (float*)&sb[AQ_ELEMS];   // 128 x BUF_LD floats (overlays K stages)
    if (s == 1) {
#pragma unroll
        for (int mt = 0; mt < 2; mt++)
#pragma unroll
            for (int half = 0; half < 2; half++) {
                int row = wq * 32 + mt * 16 + (lane >> 2) + half * 8;
#pragma unroll
                for (int nt = 0; nt < 8; nt++) {
                    int col = nt * 8 + (lane & 3) * 2;
                    buf[row * BUF_LD + col]     = O[mt][nt][half * 2];
                    buf[row * BUF_LD + col + 1] = O[mt][nt][half * 2 + 1];
                }
            }
    }
    __syncthreads();
    if (s == 0) {
#pragma unroll
        for (int mt = 0; mt < 2; mt++)
#pragma unroll
            for (int half = 0; half < 2; half++) {
                int row = wq * 32 + mt * 16 + (lane >> 2) + half * 8;
                float d0[8], d1[8];
                float ss = 0.f;
#pragma unroll
                for (int nt = 0; nt < 8; nt++) {
                    int col = nt * 8 + (lane & 3) * 2;
                    d0[nt] = O[mt][nt][half * 2]     - buf[row * BUF_LD + col];
                    d1[nt] = O[mt][nt][half * 2 + 1] - buf[row * BUF_LD + col + 1];
                    ss += d0[nt] * d0[nt] + d1[nt] * d1[nt];
                }
                ss += __shfl_xor_sync(0xffffffffu, ss, 1);
                ss += __shfl_xor_sync(0xffffffffu, ss, 2);
                float rms = sqrtf(ss * (1.f / 64.f));
                float sc = ONE_MINUS_LI / (rms + 1e-8f);
                size_t gb = ((size_t)(b * TT + q0 + row)) * 512 + h * 64;
#pragma unroll
                for (int nt = 0; nt < 8; nt++) {
                    int col = nt * 8 + (lane & 3) * 2;
                    float v0 = d0[nt] * sc * __ldg(&gamma[col]);
                    float v1 = d1[nt] * sc * __ldg(&gamma[col + 1]);
                    __nv_bfloat162 h2 = __floats2bfloat162_rn(v0, v1);
                    float2 hf = __bfloat1622float2(h2);
                    __nv_bfloat162 l2 = __floats2bfloat162_rn(v0 - hf.x, v1 - hf.y);
                    *(__nv_bfloat162*)&attn_hi[gb + col] = h2;
                    *(__nv_bfloat162*)&attn_lo[gb + col] = l2;
                }
            }
    }
}

// ---------------------------------------------------------------------------
extern "C" void kernel_launch(void* const* d_in, const int* in_sizes, int n_in,
                              void* d_out, int out_size)
{
    const float* x    = (const float*)d_in[0];
    const float* Wq   = (const float*)d_in[1];
    const float* Wkv  = (const float*)d_in[2];
    const float* Wout = (const float*)d_in[3];
    const float* lq1  = (const float*)d_in[4];
    const float* lk1  = (const float*)d_in[5];
    const float* lq2  = (const float*)d_in[6];
    const float* lk2  = (const float*)d_in[7];
    const float* gamma = (const float*)d_in[8];
    float* out = (float*)d_out;

    cudaFuncSetAttribute(gemm_qkv_tc, cudaFuncAttributeMaxDynamicSharedMemorySize,
                         GEMM_SMEM_BYTES);
    cudaFuncSetAttribute(gemm_out_tc, cudaFuncAttributeMaxDynamicSharedMemorySize,
                         GEMM_SMEM_BYTES);
    cudaFuncSetAttribute(attn2_kernel, cudaFuncAttributeMaxDynamicSharedMemorySize,
                         ATT_SMEM_BYTES);

    convx_kernel<<<4096, 256>>>(x);
    convw_kernel<<<dim3(48, 32), 256>>>(Wq, Wkv);
    convwout_kernel<<<dim3(32, 16), 256>>>(Wout);

    gemm_qkv_tc<<<dim3(12, 32), 256, GEMM_SMEM_BYTES>>>();
    vtrans_kernel<<<dim3(64, 2, 16), 256>>>();
    attn2_kernel<<<dim3(16, 8, 2), 256, ATT_SMEM_BYTES>>>(gamma, lq1, lk1, lq2, lk2);
    gemm_out_tc<<<dim3(8, 32), 256, GEMM_SMEM_BYTES>>>(out);
}